// round 6
// baseline (speedup 1.0000x reference)
#include <cuda_runtime.h>
#include <math.h>
#include <stdint.h>

#define EMB   384
#define HEADS 6
#define QD    64
#define DFF   1536
#define BB    32
#define TT    512
#define ROWS  (BB*TT)   // 16384

// ---------------- scratch (device globals; no allocation allowed) ----------------
__device__ float g_h [ROWS*EMB];
__device__ float g_q [ROWS*EMB];
__device__ float g_k [ROWS*EMB];
__device__ float g_v [ROWS*EMB];
__device__ float g_o [ROWS*EMB];
__device__ float g_h2[ROWS*EMB];
__device__ float g_ff[ROWS*DFF];

// ---------------- LayerNorm ----------------
__global__ void ln_kernel(const float* __restrict__ x,
                          const float* __restrict__ g,
                          const float* __restrict__ b,
                          float* __restrict__ out) {
    __shared__ float red[4];
    int row = blockIdx.x;
    int tid = threadIdx.x;
    const float* xr = x + (size_t)row * EMB;

    float v0 = xr[tid], v1 = xr[tid + 128], v2 = xr[tid + 256];
    float s = v0 + v1 + v2;
    #pragma unroll
    for (int o = 16; o; o >>= 1) s += __shfl_xor_sync(0xffffffffu, s, o);
    if ((tid & 31) == 0) red[tid >> 5] = s;
    __syncthreads();
    float mu = (red[0] + red[1] + red[2] + red[3]) * (1.0f / EMB);
    __syncthreads();

    float d0 = v0 - mu, d1 = v1 - mu, d2 = v2 - mu;
    float vv = d0*d0 + d1*d1 + d2*d2;
    #pragma unroll
    for (int o = 16; o; o >>= 1) vv += __shfl_xor_sync(0xffffffffu, vv, o);
    if ((tid & 31) == 0) red[tid >> 5] = vv;
    __syncthreads();
    float var = (red[0] + red[1] + red[2] + red[3]) * (1.0f / EMB);
    float inv = rsqrtf(var + 1e-5f);

    float* orow = out + (size_t)row * EMB;
    orow[tid]       = d0 * inv * g[tid]       + b[tid];
    orow[tid + 128] = d1 * inv * g[tid + 128] + b[tid + 128];
    orow[tid + 256] = d2 * inv * g[tid + 256] + b[tid + 256];
}

// ---------------- TF32 GEMM, BK=32, 3-stage cp.async, cvt.rna at frag read ----
#define A_STRIDE 36
#define B_STRIDE 136
#define A_WORDS  (128 * A_STRIDE)          // 4608
#define B_WORDS  (32  * B_STRIDE)          // 4352
#define BUF_WORDS (A_WORDS + B_WORDS)      // 8960
#define BUF_BYTES (BUF_WORDS * 4)          // 35840
#define GEMM_SMEM (3 * BUF_BYTES)          // 107520

__device__ __forceinline__ uint32_t f2tf32(float f) {
    uint32_t r;
    asm("cvt.rna.tf32.f32 %0, %1;" : "=r"(r) : "f"(f));
    return r;
}
__device__ __forceinline__ uint32_t s2tf32(uint32_t bits) {
    return f2tf32(__uint_as_float(bits));
}
__device__ __forceinline__ void cp16(uint32_t saddr, const void* gptr) {
    asm volatile("cp.async.cg.shared.global [%0], [%1], 16;"
                 :: "r"(saddr), "l"(gptr));
}

template<int EPI>
__global__ void __launch_bounds__(256)
tmma_gemm(const float* __restrict__ A, const float* __restrict__ W,
          const float* __restrict__ bias, const float* __restrict__ R,
          float* __restrict__ C, int M, int N, int K) {
    extern __shared__ uint32_t smbuf[];
    uint32_t sbase = (uint32_t)__cvta_generic_to_shared(smbuf);

    int tid  = threadIdx.x;
    int lane = tid & 31;
    int warp = tid >> 5;
    int wm   = warp >> 2;
    int wn   = warp & 3;
    int l4   = lane >> 2;
    int qq   = lane & 3;
    int n0   = blockIdx.x * 128;
    int m0   = blockIdx.y * 128;

    // loaders (BK=32): A: 128 rows x 8 float4 (2 threads/row, 4 chunks each)
    int ar  = tid >> 1;            // 0..127
    int ac  = (tid & 1) * 4;       // word col base: 0 or 4; chunks at +8i
    // B: 32 rows x 32 float4 (8 threads/row, 4 chunks each)
    int br  = tid >> 3;            // 0..31
    int bc  = (tid & 7) * 4;       // word col base; chunks at +32i

    const float* Ap = &A[(size_t)(m0 + ar) * K + ac];
    const float* Bp = &W[(size_t)br * N + n0 + bc];
    uint32_t sA = sbase + (ar * A_STRIDE + ac) * 4;
    uint32_t sB = sbase + (A_WORDS + br * B_STRIDE + bc) * 4;

    float acc[4][4][4];
    #pragma unroll
    for (int mt = 0; mt < 4; mt++)
        #pragma unroll
        for (int nt = 0; nt < 4; nt++)
            #pragma unroll
            for (int e = 0; e < 4; e++) acc[mt][nt][e] = 0.f;

    int nsteps = K >> 5;

    #pragma unroll
    for (int s = 0; s < 2; s++) {
        uint32_t off = s * BUF_BYTES;
        int k0 = s << 5;
        #pragma unroll
        for (int i = 0; i < 4; i++) {
            cp16(sA + off + i * 32,  Ap + k0 + 8 * i);                 // +8 words = 32B
            cp16(sB + off + i * 128, Bp + (size_t)k0 * N + 32 * i);    // +32 words = 128B
        }
        asm volatile("cp.async.commit_group;");
    }
    asm volatile("cp.async.wait_group 1;");
    __syncthreads();

    int cur = 0;
    for (int s = 0; s < nsteps; s++) {
        uint32_t* As = smbuf + cur * BUF_WORDS;
        uint32_t* Bs = smbuf + cur * BUF_WORDS + A_WORDS;

        #pragma unroll
        for (int kk = 0; kk < 4; kk++) {
            int kb = kk * 8;
            uint32_t af[4][4], bf[4][2];
            #pragma unroll
            for (int mt = 0; mt < 4; mt++) {
                int mrow = wm * 64 + mt * 16 + l4;
                af[mt][0] = s2tf32(As[mrow * A_STRIDE + kb + qq]);
                af[mt][1] = s2tf32(As[(mrow + 8) * A_STRIDE + kb + qq]);
                af[mt][2] = s2tf32(As[mrow * A_STRIDE + kb + qq + 4]);
                af[mt][3] = s2tf32(As[(mrow + 8) * A_STRIDE + kb + qq + 4]);
            }
            #pragma unroll
            for (int nt = 0; nt < 4; nt++) {
                int nc = wn * 32 + nt * 8 + l4;
                bf[nt][0] = s2tf32(Bs[(kb + qq) * B_STRIDE + nc]);
                bf[nt][1] = s2tf32(Bs[(kb + qq + 4) * B_STRIDE + nc]);
            }
            #pragma unroll
            for (int mt = 0; mt < 4; mt++)
                #pragma unroll
                for (int nt = 0; nt < 4; nt++)
                    asm volatile(
                        "mma.sync.aligned.m16n8k8.row.col.f32.tf32.tf32.f32 "
                        "{%0,%1,%2,%3}, {%4,%5,%6,%7}, {%8,%9}, {%0,%1,%2,%3};"
                        : "+f"(acc[mt][nt][0]), "+f"(acc[mt][nt][1]),
                          "+f"(acc[mt][nt][2]), "+f"(acc[mt][nt][3])
                        : "r"(af[mt][0]), "r"(af[mt][1]), "r"(af[mt][2]), "r"(af[mt][3]),
                          "r"(bf[nt][0]), "r"(bf[nt][1]));
        }

        int nx = s + 2;
        if (nx < nsteps) {
            uint32_t off = (uint32_t)(nx % 3) * BUF_BYTES;
            int k0 = nx << 5;
            #pragma unroll
            for (int i = 0; i < 4; i++) {
                cp16(sA + off + i * 32,  Ap + k0 + 8 * i);
                cp16(sB + off + i * 128, Bp + (size_t)k0 * N + 32 * i);
            }
            asm volatile("cp.async.commit_group;");
            asm volatile("cp.async.wait_group 1;");
        } else {
            asm volatile("cp.async.wait_group 0;");
        }
        __syncthreads();
        cur = (cur + 1) % 3;
    }

    #pragma unroll
    for (int mt = 0; mt < 4; mt++) {
        #pragma unroll
        for (int nt = 0; nt < 4; nt++) {
            #pragma unroll
            for (int e = 0; e < 4; e++) {
                int m = m0 + wm * 64 + mt * 16 + l4 + ((e >= 2) ? 8 : 0);
                int n = n0 + wn * 32 + nt * 8 + qq * 2 + (e & 1);
                float val = acc[mt][nt][e];
                if (EPI == 0) {
                    int b_ = m >> 9, t_ = m & 511;
                    int head = n >> 6, d = n & 63;
                    C[(((size_t)(b_ * HEADS + head)) * TT + t_) * 64 + d] = val;
                } else if (EPI == 1) {
                    C[(size_t)m * N + n] = val + bias[n] + R[(size_t)m * N + n];
                } else {
                    val += bias[n];
                    C[(size_t)m * N + n] = val > 0.f ? val : 0.f;
                }
            }
        }
    }
}

// ---------------- tensor flash attention, cp.async K/V double-buffer ----------------
// smem (words): K0[64*72] K1[64*72] V0[64*72] V1[64*72] P[128*72]
#define ASTR 72
#define KV_WORDS (64 * ASTR)                 // 4608
#define AT_K0 0
#define AT_K1 KV_WORDS
#define AT_V0 (2 * KV_WORDS)
#define AT_V1 (3 * KV_WORDS)
#define AT_P  (4 * KV_WORDS)                 // 18432; P = 128*72 = 9216
#define ATTN2_WORDS (AT_P + 128 * ASTR)      // 27648
#define ATTN2_SMEM (ATTN2_WORDS * 4)         // 110592

__global__ void __launch_bounds__(256)
attn2_kernel(const float* __restrict__ q, const float* __restrict__ k,
             const float* __restrict__ v, float* __restrict__ o) {
    extern __shared__ uint32_t sm2[];
    uint32_t sbase = (uint32_t)__cvta_generic_to_shared(sm2);
    uint32_t* Ps = sm2 + AT_P;

    int tid  = threadIdx.x;
    int lane = tid & 31;
    int warp = tid >> 5;
    int l4   = lane >> 2;
    int qq   = lane & 3;
    int bh   = blockIdx.y;
    int q0   = blockIdx.x * 128;

    int mrow = warp * 16 + l4;
    int qg0  = q0 + mrow;
    int qg1  = qg0 + 8;
    int ktiles = (q0 + 128) >> 6;

    int lrow = tid >> 4;            // 0..15 (KV loader: +16 per it)
    int lc4  = (tid & 15) * 4;
    const float* kgb = k + ((size_t)bh * TT) * 64;
    const float* vgb = v + ((size_t)bh * TT) * 64;

    // prefetch tile 0 (raw fp32)
    {
        uint32_t kd = sbase + (AT_K0 + lrow * ASTR + lc4) * 4;
        uint32_t vd = sbase + (AT_V0 + lrow * ASTR + lc4) * 4;
        const float* kg = kgb + (size_t)lrow * 64 + lc4;
        const float* vg = vgb + (size_t)lrow * 64 + lc4;
        #pragma unroll
        for (int it = 0; it < 4; it++) {
            cp16(kd + it * 16 * ASTR * 4, kg + it * 16 * 64);
            cp16(vd + it * 16 * ASTR * 4, vg + it * 16 * 64);
        }
        asm volatile("cp.async.commit_group;");
    }

    // stage Q into P region (tf32, scaled), then hoist fragments to registers
    {
        const float4* qb = (const float4*)(q + ((size_t)bh * TT + q0) * 64);
        #pragma unroll
        for (int it = 0; it < 8; it++) {
            int i   = tid + it * 256;
            int row = i >> 4, c4 = (i & 15) * 4;
            float4 t = qb[i];
            uint4 u;
            u.x = f2tf32(t.x * 0.125f); u.y = f2tf32(t.y * 0.125f);
            u.z = f2tf32(t.z * 0.125f); u.w = f2tf32(t.w * 0.125f);
            *(uint4*)&Ps[row * ASTR + c4] = u;
        }
    }
    __syncthreads();

    uint32_t qf[8][4];
    #pragma unroll
    for (int kk = 0; kk < 8; kk++) {
        int kb = kk * 8;
        qf[kk][0] = Ps[mrow * ASTR + kb + qq];
        qf[kk][1] = Ps[(mrow + 8) * ASTR + kb + qq];
        qf[kk][2] = Ps[mrow * ASTR + kb + qq + 4];
        qf[kk][3] = Ps[(mrow + 8) * ASTR + kb + qq + 4];
    }

    float Oa[8][4];
    #pragma unroll
    for (int nt = 0; nt < 8; nt++)
        #pragma unroll
        for (int e = 0; e < 4; e++) Oa[nt][e] = 0.f;
    float m0 = -1e30f, m1 = -1e30f, l0 = 0.f, l1 = 0.f;

    for (int kt = 0; kt < ktiles; kt++) {
        asm volatile("cp.async.wait_group 0;");
        __syncthreads();

        if (kt + 1 < ktiles) {
            int nb = (kt + 1) & 1;
            int k0n = (kt + 1) << 6;
            uint32_t kd = sbase + ((nb ? AT_K1 : AT_K0) + lrow * ASTR + lc4) * 4;
            uint32_t vd = sbase + ((nb ? AT_V1 : AT_V0) + lrow * ASTR + lc4) * 4;
            const float* kg = kgb + (size_t)(k0n + lrow) * 64 + lc4;
            const float* vg = vgb + (size_t)(k0n + lrow) * 64 + lc4;
            #pragma unroll
            for (int it = 0; it < 4; it++) {
                cp16(kd + it * 16 * ASTR * 4, kg + it * 16 * 64);
                cp16(vd + it * 16 * ASTR * 4, vg + it * 16 * 64);
            }
            asm volatile("cp.async.commit_group;");
        }

        uint32_t* Ks = sm2 + ((kt & 1) ? AT_K1 : AT_K0);
        uint32_t* Vs = sm2 + ((kt & 1) ? AT_V1 : AT_V0);
        int k0 = kt << 6;

        // ---- S = Q @ K^T ----
        float s[8][4];
        #pragma unroll
        for (int nt = 0; nt < 8; nt++)
            #pragma unroll
            for (int e = 0; e < 4; e++) s[nt][e] = 0.f;

        #pragma unroll
        for (int kk = 0; kk < 8; kk++) {
            int kb = kk * 8;
            #pragma unroll
            for (int nt = 0; nt < 8; nt++) {
                uint32_t b0 = s2tf32(Ks[(nt * 8 + l4) * ASTR + kb + qq]);
                uint32_t b1 = s2tf32(Ks[(nt * 8 + l4) * ASTR + kb + qq + 4]);
                asm volatile(
                    "mma.sync.aligned.m16n8k8.row.col.f32.tf32.tf32.f32 "
                    "{%0,%1,%2,%3}, {%4,%5,%6,%7}, {%8,%9}, {%0,%1,%2,%3};"
                    : "+f"(s[nt][0]), "+f"(s[nt][1]), "+f"(s[nt][2]), "+f"(s[nt][3])
                    : "r"(qf[kk][0]), "r"(qf[kk][1]), "r"(qf[kk][2]), "r"(qf[kk][3]),
                      "r"(b0), "r"(b1));
            }
        }

        // ---- causal mask ----
        if (k0 + 63 > qg0) {
            #pragma unroll
            for (int nt = 0; nt < 8; nt++) {
                int kg = k0 + nt * 8 + 2 * qq;
                if (kg     > qg0) s[nt][0] = -1e30f;
                if (kg + 1 > qg0) s[nt][1] = -1e30f;
                if (kg     > qg1) s[nt][2] = -1e30f;
                if (kg + 1 > qg1) s[nt][3] = -1e30f;
            }
        }

        // ---- online softmax ----
        float r0 = -1e30f, r1 = -1e30f;
        #pragma unroll
        for (int nt = 0; nt < 8; nt++) {
            r0 = fmaxf(r0, fmaxf(s[nt][0], s[nt][1]));
            r1 = fmaxf(r1, fmaxf(s[nt][2], s[nt][3]));
        }
        r0 = fmaxf(r0, __shfl_xor_sync(0xffffffffu, r0, 1));
        r0 = fmaxf(r0, __shfl_xor_sync(0xffffffffu, r0, 2));
        r1 = fmaxf(r1, __shfl_xor_sync(0xffffffffu, r1, 1));
        r1 = fmaxf(r1, __shfl_xor_sync(0xffffffffu, r1, 2));

        float mn0 = fmaxf(m0, r0), mn1 = fmaxf(m1, r1);
        float sc0 = __expf(m0 - mn0), sc1 = __expf(m1 - mn1);
        float rs0 = 0.f, rs1 = 0.f;
        #pragma unroll
        for (int nt = 0; nt < 8; nt++) {
            s[nt][0] = __expf(s[nt][0] - mn0);
            s[nt][1] = __expf(s[nt][1] - mn0);
            s[nt][2] = __expf(s[nt][2] - mn1);
            s[nt][3] = __expf(s[nt][3] - mn1);
            rs0 += s[nt][0] + s[nt][1];
            rs1 += s[nt][2] + s[nt][3];
        }
        rs0 += __shfl_xor_sync(0xffffffffu, rs0, 1);
        rs0 += __shfl_xor_sync(0xffffffffu, rs0, 2);
        rs1 += __shfl_xor_sync(0xffffffffu, rs1, 1);
        rs1 += __shfl_xor_sync(0xffffffffu, rs1, 2);
        l0 = l0 * sc0 + rs0;
        l1 = l1 * sc1 + rs1;
        m0 = mn0; m1 = mn1;

        #pragma unroll
        for (int nt = 0; nt < 8; nt++) {
            Oa[nt][0] *= sc0; Oa[nt][1] *= sc0;
            Oa[nt][2] *= sc1; Oa[nt][3] *= sc1;
        }

        // ---- P -> warp-private smem rows (tf32) ----
        #pragma unroll
        for (int nt = 0; nt < 8; nt++) {
            uint2 u;
            u.x = f2tf32(s[nt][0]); u.y = f2tf32(s[nt][1]);
            *(uint2*)&Ps[mrow * ASTR + nt * 8 + 2 * qq] = u;
            u.x = f2tf32(s[nt][2]); u.y = f2tf32(s[nt][3]);
            *(uint2*)&Ps[(mrow + 8) * ASTR + nt * 8 + 2 * qq] = u;
        }
        __syncwarp();

        // ---- O += P @ V ----
        #pragma unroll
        for (int kk = 0; kk < 8; kk++) {
            int kb = kk * 8;
            uint32_t af[4];
            af[0] = Ps[mrow * ASTR + kb + qq];
            af[1] = Ps[(mrow + 8) * ASTR + kb + qq];
            af[2] = Ps[mrow * ASTR + kb + qq + 4];
            af[3] = Ps[(mrow + 8) * ASTR + kb + qq + 4];
            #pragma unroll
            for (int nt = 0; nt < 8; nt++) {
                uint32_t b0 = s2tf32(Vs[(kb + qq) * ASTR + nt * 8 + l4]);
                uint32_t b1 = s2tf32(Vs[(kb + qq + 4) * ASTR + nt * 8 + l4]);
                asm volatile(
                    "mma.sync.aligned.m16n8k8.row.col.f32.tf32.tf32.f32 "
                    "{%0,%1,%2,%3}, {%4,%5,%6,%7}, {%8,%9}, {%0,%1,%2,%3};"
                    : "+f"(Oa[nt][0]), "+f"(Oa[nt][1]), "+f"(Oa[nt][2]), "+f"(Oa[nt][3])
                    : "r"(af[0]), "r"(af[1]), "r"(af[2]), "r"(af[3]),
                      "r"(b0), "r"(b1));
            }
        }
    }

    int b_ = bh / HEADS, h_ = bh % HEADS;
    float inv0 = 1.f / l0, inv1 = 1.f / l1;
    float* ob0 = o + ((size_t)(b_ * TT + qg0)) * EMB + h_ * 64;
    float* ob1 = o + ((size_t)(b_ * TT + qg1)) * EMB + h_ * 64;
    #pragma unroll
    for (int nt = 0; nt < 8; nt++) {
        float2 t0 = make_float2(Oa[nt][0] * inv0, Oa[nt][1] * inv0);
        float2 t1 = make_float2(Oa[nt][2] * inv1, Oa[nt][3] * inv1);
        *(float2*)&ob0[nt * 8 + 2 * qq] = t0;
        *(float2*)&ob1[nt * 8 + 2 * qq] = t1;
    }
}

// ---------------- launch ----------------
extern "C" void kernel_launch(void* const* d_in, const int* in_sizes, int n_in,
                              void* d_out, int out_size) {
    const float* x   = (const float*)d_in[0];
    const float* Wq  = (const float*)d_in[1];
    const float* Wk  = (const float*)d_in[2];
    const float* Wv  = (const float*)d_in[3];
    const float* Wp  = (const float*)d_in[4];
    const float* bp  = (const float*)d_in[5];
    const float* g1  = (const float*)d_in[6];
    const float* b1  = (const float*)d_in[7];
    const float* g2  = (const float*)d_in[8];
    const float* b2  = (const float*)d_in[9];
    const float* W1  = (const float*)d_in[10];
    const float* bf1 = (const float*)d_in[11];
    const float* W2  = (const float*)d_in[12];
    const float* bf2 = (const float*)d_in[13];
    float* out = (float*)d_out;

    float *h, *q, *k, *v, *o, *h2, *ff;
    cudaGetSymbolAddress((void**)&h,  g_h);
    cudaGetSymbolAddress((void**)&q,  g_q);
    cudaGetSymbolAddress((void**)&k,  g_k);
    cudaGetSymbolAddress((void**)&v,  g_v);
    cudaGetSymbolAddress((void**)&o,  g_o);
    cudaGetSymbolAddress((void**)&h2, g_h2);
    cudaGetSymbolAddress((void**)&ff, g_ff);

    static bool attr_done = false;
    if (!attr_done) {
        cudaFuncSetAttribute(attn2_kernel, cudaFuncAttributeMaxDynamicSharedMemorySize,
                             (int)ATTN2_SMEM);
        cudaFuncSetAttribute(tmma_gemm<0>, cudaFuncAttributeMaxDynamicSharedMemorySize,
                             (int)GEMM_SMEM);
        cudaFuncSetAttribute(tmma_gemm<1>, cudaFuncAttributeMaxDynamicSharedMemorySize,
                             (int)GEMM_SMEM);
        cudaFuncSetAttribute(tmma_gemm<2>, cudaFuncAttributeMaxDynamicSharedMemorySize,
                             (int)GEMM_SMEM);
        attr_done = true;
    }

    // 1) ln1
    ln_kernel<<<ROWS, 128>>>(x, g1, b1, h);

    // 2) QKV projections
    {
        dim3 grid(EMB / 128, ROWS / 128);
        tmma_gemm<0><<<grid, 256, GEMM_SMEM>>>(h, Wq, nullptr, nullptr, q, ROWS, EMB, EMB);
        tmma_gemm<0><<<grid, 256, GEMM_SMEM>>>(h, Wk, nullptr, nullptr, k, ROWS, EMB, EMB);
        tmma_gemm<0><<<grid, 256, GEMM_SMEM>>>(h, Wv, nullptr, nullptr, v, ROWS, EMB, EMB);
    }

    // 3) causal attention
    {
        dim3 grid(TT / 128, BB * HEADS);
        attn2_kernel<<<grid, 256, ATTN2_SMEM>>>(q, k, v, o);
    }

    // 4) out projection + residual -> d_out
    {
        dim3 grid(EMB / 128, ROWS / 128);
        tmma_gemm<1><<<grid, 256, GEMM_SMEM>>>(o, Wp, bp, x, out, ROWS, EMB, EMB);
    }

    // 5) ln2
    ln_kernel<<<ROWS, 128>>>(out, g2, b2, h2);

    // 6) FF1
    {
        dim3 grid(DFF / 128, ROWS / 128);
        tmma_gemm<2><<<grid, 256, GEMM_SMEM>>>(h2, W1, bf1, nullptr, ff, ROWS, DFF, EMB);
    }

    // 7) FF2
    {
        dim3 grid(EMB / 128, ROWS / 128);
        tmma_gemm<1><<<grid, 256, GEMM_SMEM>>>(ff, W2, bf2, out, out, ROWS, EMB, DFF);
    }
}

// round 7
// speedup vs baseline: 1.0691x; 1.0691x over previous
#include <cuda_runtime.h>
#include <math.h>
#include <stdint.h>

#define EMB   384
#define HEADS 6
#define QD    64
#define DFF   1536
#define BB    32
#define TT    512
#define ROWS  (BB*TT)   // 16384

// ---------------- scratch (device globals; no allocation allowed) ----------------
__device__ float g_h [ROWS*EMB];
__device__ float g_q [ROWS*EMB];
__device__ float g_k [ROWS*EMB];
__device__ float g_v [ROWS*EMB];
__device__ float g_o [ROWS*EMB];
__device__ float g_h2[ROWS*EMB];
__device__ float g_ff[ROWS*DFF];
// tf32-rounded weight copies
__device__ float g_wq[EMB*EMB];
__device__ float g_wk[EMB*EMB];
__device__ float g_wv[EMB*EMB];
__device__ float g_wp[EMB*EMB];
__device__ float g_w1[EMB*DFF];
__device__ float g_w2[DFF*EMB];

__device__ __forceinline__ uint32_t f2tf32(float f) {
    uint32_t r;
    asm("cvt.rna.tf32.f32 %0, %1;" : "=r"(r) : "f"(f));
    return r;
}
__device__ __forceinline__ float rnd32(float f) {
    return __uint_as_float(f2tf32(f));
}
__device__ __forceinline__ void cp16(uint32_t saddr, const void* gptr) {
    asm volatile("cp.async.cg.shared.global [%0], [%1], 16;"
                 :: "r"(saddr), "l"(gptr));
}

// ---------------- weight pre-round: dst = tf32_rna(src) ----------------
__global__ void round_w_kernel(const float* __restrict__ src,
                               float* __restrict__ dst, int n4) {
    int i = blockIdx.x * blockDim.x + threadIdx.x;
    if (i < n4) {
        float4 t = ((const float4*)src)[i];
        t.x = rnd32(t.x); t.y = rnd32(t.y); t.z = rnd32(t.z); t.w = rnd32(t.w);
        ((float4*)dst)[i] = t;
    }
}

// ---------------- LayerNorm (tf32-rounded output) ----------------
__global__ void ln_kernel(const float* __restrict__ x,
                          const float* __restrict__ g,
                          const float* __restrict__ b,
                          float* __restrict__ out) {
    __shared__ float red[4];
    int row = blockIdx.x;
    int tid = threadIdx.x;
    const float* xr = x + (size_t)row * EMB;

    float v0 = xr[tid], v1 = xr[tid + 128], v2 = xr[tid + 256];
    float s = v0 + v1 + v2;
    #pragma unroll
    for (int o = 16; o; o >>= 1) s += __shfl_xor_sync(0xffffffffu, s, o);
    if ((tid & 31) == 0) red[tid >> 5] = s;
    __syncthreads();
    float mu = (red[0] + red[1] + red[2] + red[3]) * (1.0f / EMB);
    __syncthreads();

    float d0 = v0 - mu, d1 = v1 - mu, d2 = v2 - mu;
    float vv = d0*d0 + d1*d1 + d2*d2;
    #pragma unroll
    for (int o = 16; o; o >>= 1) vv += __shfl_xor_sync(0xffffffffu, vv, o);
    if ((tid & 31) == 0) red[tid >> 5] = vv;
    __syncthreads();
    float var = (red[0] + red[1] + red[2] + red[3]) * (1.0f / EMB);
    float inv = rsqrtf(var + 1e-5f);

    float* orow = out + (size_t)row * EMB;
    orow[tid]       = rnd32(d0 * inv * g[tid]       + b[tid]);
    orow[tid + 128] = rnd32(d1 * inv * g[tid + 128] + b[tid + 128]);
    orow[tid + 256] = rnd32(d2 * inv * g[tid + 256] + b[tid + 256]);
}

// ---------------- TF32 GEMM, BK=32, 3-stage cp.async, raw tf32 operands ----
#define A_STRIDE 36
#define B_STRIDE 136
#define A_WORDS  (128 * A_STRIDE)          // 4608
#define B_WORDS  (32  * B_STRIDE)          // 4352
#define BUF_WORDS (A_WORDS + B_WORDS)      // 8960
#define BUF_BYTES (BUF_WORDS * 4)          // 35840
#define GEMM_SMEM (3 * BUF_BYTES)          // 107520

// EPI: 0 = tf32-rounded scatter to [B,H,T,D]; 1 = +bias +residual (fp32, NOT rounded);
//      2 = +bias +relu, tf32-rounded
template<int EPI>
__global__ void __launch_bounds__(256)
tmma_gemm(const float* __restrict__ A, const float* __restrict__ W,
          const float* __restrict__ bias, const float* __restrict__ R,
          float* __restrict__ C, int M, int N, int K) {
    extern __shared__ uint32_t smbuf[];
    uint32_t sbase = (uint32_t)__cvta_generic_to_shared(smbuf);

    int tid  = threadIdx.x;
    int lane = tid & 31;
    int warp = tid >> 5;
    int wm   = warp >> 2;
    int wn   = warp & 3;
    int l4   = lane >> 2;
    int qq   = lane & 3;
    int n0   = blockIdx.x * 128;
    int m0   = blockIdx.y * 128;

    int ar  = tid >> 1;            // 0..127
    int ac  = (tid & 1) * 4;       // 0 or 4; chunks at +8i
    int br  = tid >> 3;            // 0..31
    int bc  = (tid & 7) * 4;       // chunks at +32i

    const float* Ap = &A[(size_t)(m0 + ar) * K + ac];
    const float* Bp = &W[(size_t)br * N + n0 + bc];
    uint32_t sA = sbase + (ar * A_STRIDE + ac) * 4;
    uint32_t sB = sbase + (A_WORDS + br * B_STRIDE + bc) * 4;

    float acc[4][4][4];
    #pragma unroll
    for (int mt = 0; mt < 4; mt++)
        #pragma unroll
        for (int nt = 0; nt < 4; nt++)
            #pragma unroll
            for (int e = 0; e < 4; e++) acc[mt][nt][e] = 0.f;

    int nsteps = K >> 5;

    #pragma unroll
    for (int s = 0; s < 2; s++) {
        uint32_t off = s * BUF_BYTES;
        int k0 = s << 5;
        #pragma unroll
        for (int i = 0; i < 4; i++) {
            cp16(sA + off + i * 32,  Ap + k0 + 8 * i);
            cp16(sB + off + i * 128, Bp + (size_t)k0 * N + 32 * i);
        }
        asm volatile("cp.async.commit_group;");
    }
    asm volatile("cp.async.wait_group 1;");
    __syncthreads();

    int cur = 0;
    for (int s = 0; s < nsteps; s++) {
        uint32_t* As = smbuf + cur * BUF_WORDS;
        uint32_t* Bs = smbuf + cur * BUF_WORDS + A_WORDS;

        #pragma unroll
        for (int kk = 0; kk < 4; kk++) {
            int kb = kk * 8;
            uint32_t af[4][4], bf[4][2];
            #pragma unroll
            for (int mt = 0; mt < 4; mt++) {
                int mrow = wm * 64 + mt * 16 + l4;
                af[mt][0] = As[mrow * A_STRIDE + kb + qq];
                af[mt][1] = As[(mrow + 8) * A_STRIDE + kb + qq];
                af[mt][2] = As[mrow * A_STRIDE + kb + qq + 4];
                af[mt][3] = As[(mrow + 8) * A_STRIDE + kb + qq + 4];
            }
            #pragma unroll
            for (int nt = 0; nt < 4; nt++) {
                int nc = wn * 32 + nt * 8 + l4;
                bf[nt][0] = Bs[(kb + qq) * B_STRIDE + nc];
                bf[nt][1] = Bs[(kb + qq + 4) * B_STRIDE + nc];
            }
            #pragma unroll
            for (int mt = 0; mt < 4; mt++)
                #pragma unroll
                for (int nt = 0; nt < 4; nt++)
                    asm volatile(
                        "mma.sync.aligned.m16n8k8.row.col.f32.tf32.tf32.f32 "
                        "{%0,%1,%2,%3}, {%4,%5,%6,%7}, {%8,%9}, {%0,%1,%2,%3};"
                        : "+f"(acc[mt][nt][0]), "+f"(acc[mt][nt][1]),
                          "+f"(acc[mt][nt][2]), "+f"(acc[mt][nt][3])
                        : "r"(af[mt][0]), "r"(af[mt][1]), "r"(af[mt][2]), "r"(af[mt][3]),
                          "r"(bf[nt][0]), "r"(bf[nt][1]));
        }

        int nx = s + 2;
        if (nx < nsteps) {
            uint32_t off = (uint32_t)(nx % 3) * BUF_BYTES;
            int k0 = nx << 5;
            #pragma unroll
            for (int i = 0; i < 4; i++) {
                cp16(sA + off + i * 32,  Ap + k0 + 8 * i);
                cp16(sB + off + i * 128, Bp + (size_t)k0 * N + 32 * i);
            }
            asm volatile("cp.async.commit_group;");
            asm volatile("cp.async.wait_group 1;");
        } else {
            asm volatile("cp.async.wait_group 0;");
        }
        __syncthreads();
        cur = (cur + 1) % 3;
    }

    #pragma unroll
    for (int mt = 0; mt < 4; mt++) {
        #pragma unroll
        for (int nt = 0; nt < 4; nt++) {
            #pragma unroll
            for (int e = 0; e < 4; e++) {
                int m = m0 + wm * 64 + mt * 16 + l4 + ((e >= 2) ? 8 : 0);
                int n = n0 + wn * 32 + nt * 8 + qq * 2 + (e & 1);
                float val = acc[mt][nt][e];
                if (EPI == 0) {
                    int b_ = m >> 9, t_ = m & 511;
                    int head = n >> 6, d = n & 63;
                    C[(((size_t)(b_ * HEADS + head)) * TT + t_) * 64 + d] = rnd32(val);
                } else if (EPI == 1) {
                    C[(size_t)m * N + n] = val + bias[n] + R[(size_t)m * N + n];
                } else {
                    val += bias[n];
                    C[(size_t)m * N + n] = rnd32(val > 0.f ? val : 0.f);
                }
            }
        }
    }
}

// ---------------- tensor flash attention, cp.async K/V double-buffer ----------------
// q,k,v are already tf32-rounded. O output tf32-rounded (A of Wp GEMM).
#define ASTR 72
#define KV_WORDS (64 * ASTR)                 // 4608
#define AT_K0 0
#define AT_K1 KV_WORDS
#define AT_V0 (2 * KV_WORDS)
#define AT_V1 (3 * KV_WORDS)
#define AT_P  (4 * KV_WORDS)                 // 18432
#define ATTN2_WORDS (AT_P + 128 * ASTR)      // 27648
#define ATTN2_SMEM (ATTN2_WORDS * 4)         // 110592

__global__ void __launch_bounds__(256)
attn2_kernel(const float* __restrict__ q, const float* __restrict__ k,
             const float* __restrict__ v, float* __restrict__ o) {
    extern __shared__ uint32_t sm2[];
    uint32_t sbase = (uint32_t)__cvta_generic_to_shared(sm2);
    uint32_t* Ps = sm2 + AT_P;

    int tid  = threadIdx.x;
    int lane = tid & 31;
    int warp = tid >> 5;
    int l4   = lane >> 2;
    int qq   = lane & 3;
    int bh   = blockIdx.y;
    int q0   = blockIdx.x * 128;

    int mrow = warp * 16 + l4;
    int qg0  = q0 + mrow;
    int qg1  = qg0 + 8;
    int ktiles = (q0 + 128) >> 6;

    int lrow = tid >> 4;
    int lc4  = (tid & 15) * 4;
    const float* kgb = k + ((size_t)bh * TT) * 64;
    const float* vgb = v + ((size_t)bh * TT) * 64;

    // prefetch tile 0
    {
        uint32_t kd = sbase + (AT_K0 + lrow * ASTR + lc4) * 4;
        uint32_t vd = sbase + (AT_V0 + lrow * ASTR + lc4) * 4;
        const float* kg = kgb + (size_t)lrow * 64 + lc4;
        const float* vg = vgb + (size_t)lrow * 64 + lc4;
        #pragma unroll
        for (int it = 0; it < 4; it++) {
            cp16(kd + it * 16 * ASTR * 4, kg + it * 16 * 64);
            cp16(vd + it * 16 * ASTR * 4, vg + it * 16 * 64);
        }
        asm volatile("cp.async.commit_group;");
    }

    // stage Q (x0.125 is exact on tf32 values)
    {
        const float4* qb = (const float4*)(q + ((size_t)bh * TT + q0) * 64);
        #pragma unroll
        for (int it = 0; it < 8; it++) {
            int i   = tid + it * 256;
            int row = i >> 4, c4 = (i & 15) * 4;
            float4 t = qb[i];
            uint4 u;
            u.x = __float_as_uint(t.x * 0.125f);
            u.y = __float_as_uint(t.y * 0.125f);
            u.z = __float_as_uint(t.z * 0.125f);
            u.w = __float_as_uint(t.w * 0.125f);
            *(uint4*)&Ps[row * ASTR + c4] = u;
        }
    }
    __syncthreads();

    uint32_t qf[8][4];
    #pragma unroll
    for (int kk = 0; kk < 8; kk++) {
        int kb = kk * 8;
        qf[kk][0] = Ps[mrow * ASTR + kb + qq];
        qf[kk][1] = Ps[(mrow + 8) * ASTR + kb + qq];
        qf[kk][2] = Ps[mrow * ASTR + kb + qq + 4];
        qf[kk][3] = Ps[(mrow + 8) * ASTR + kb + qq + 4];
    }

    float Oa[8][4];
    #pragma unroll
    for (int nt = 0; nt < 8; nt++)
        #pragma unroll
        for (int e = 0; e < 4; e++) Oa[nt][e] = 0.f;
    float m0 = -1e30f, m1 = -1e30f, l0 = 0.f, l1 = 0.f;

    for (int kt = 0; kt < ktiles; kt++) {
        asm volatile("cp.async.wait_group 0;");
        __syncthreads();

        if (kt + 1 < ktiles) {
            int nb = (kt + 1) & 1;
            int k0n = (kt + 1) << 6;
            uint32_t kd = sbase + ((nb ? AT_K1 : AT_K0) + lrow * ASTR + lc4) * 4;
            uint32_t vd = sbase + ((nb ? AT_V1 : AT_V0) + lrow * ASTR + lc4) * 4;
            const float* kg = kgb + (size_t)(k0n + lrow) * 64 + lc4;
            const float* vg = vgb + (size_t)(k0n + lrow) * 64 + lc4;
            #pragma unroll
            for (int it = 0; it < 4; it++) {
                cp16(kd + it * 16 * ASTR * 4, kg + it * 16 * 64);
                cp16(vd + it * 16 * ASTR * 4, vg + it * 16 * 64);
            }
            asm volatile("cp.async.commit_group;");
        }

        uint32_t* Ks = sm2 + ((kt & 1) ? AT_K1 : AT_K0);
        uint32_t* Vs = sm2 + ((kt & 1) ? AT_V1 : AT_V0);
        int k0 = kt << 6;

        // ---- S = Q @ K^T ----
        float s[8][4];
        #pragma unroll
        for (int nt = 0; nt < 8; nt++)
            #pragma unroll
            for (int e = 0; e < 4; e++) s[nt][e] = 0.f;

        #pragma unroll
        for (int kk = 0; kk < 8; kk++) {
            int kb = kk * 8;
            #pragma unroll
            for (int nt = 0; nt < 8; nt++) {
                uint32_t b0 = Ks[(nt * 8 + l4) * ASTR + kb + qq];
                uint32_t b1 = Ks[(nt * 8 + l4) * ASTR + kb + qq + 4];
                asm volatile(
                    "mma.sync.aligned.m16n8k8.row.col.f32.tf32.tf32.f32 "
                    "{%0,%1,%2,%3}, {%4,%5,%6,%7}, {%8,%9}, {%0,%1,%2,%3};"
                    : "+f"(s[nt][0]), "+f"(s[nt][1]), "+f"(s[nt][2]), "+f"(s[nt][3])
                    : "r"(qf[kk][0]), "r"(qf[kk][1]), "r"(qf[kk][2]), "r"(qf[kk][3]),
                      "r"(b0), "r"(b1));
            }
        }

        // ---- causal mask ----
        if (k0 + 63 > qg0) {
            #pragma unroll
            for (int nt = 0; nt < 8; nt++) {
                int kg = k0 + nt * 8 + 2 * qq;
                if (kg     > qg0) s[nt][0] = -1e30f;
                if (kg + 1 > qg0) s[nt][1] = -1e30f;
                if (kg     > qg1) s[nt][2] = -1e30f;
                if (kg + 1 > qg1) s[nt][3] = -1e30f;
            }
        }

        // ---- online softmax ----
        float r0 = -1e30f, r1 = -1e30f;
        #pragma unroll
        for (int nt = 0; nt < 8; nt++) {
            r0 = fmaxf(r0, fmaxf(s[nt][0], s[nt][1]));
            r1 = fmaxf(r1, fmaxf(s[nt][2], s[nt][3]));
        }
        r0 = fmaxf(r0, __shfl_xor_sync(0xffffffffu, r0, 1));
        r0 = fmaxf(r0, __shfl_xor_sync(0xffffffffu, r0, 2));
        r1 = fmaxf(r1, __shfl_xor_sync(0xffffffffu, r1, 1));
        r1 = fmaxf(r1, __shfl_xor_sync(0xffffffffu, r1, 2));

        float mn0 = fmaxf(m0, r0), mn1 = fmaxf(m1, r1);
        float sc0 = __expf(m0 - mn0), sc1 = __expf(m1 - mn1);
        float rs0 = 0.f, rs1 = 0.f;
        #pragma unroll
        for (int nt = 0; nt < 8; nt++) {
            s[nt][0] = __expf(s[nt][0] - mn0);
            s[nt][1] = __expf(s[nt][1] - mn0);
            s[nt][2] = __expf(s[nt][2] - mn1);
            s[nt][3] = __expf(s[nt][3] - mn1);
            rs0 += s[nt][0] + s[nt][1];
            rs1 += s[nt][2] + s[nt][3];
        }
        rs0 += __shfl_xor_sync(0xffffffffu, rs0, 1);
        rs0 += __shfl_xor_sync(0xffffffffu, rs0, 2);
        rs1 += __shfl_xor_sync(0xffffffffu, rs1, 1);
        rs1 += __shfl_xor_sync(0xffffffffu, rs1, 2);
        l0 = l0 * sc0 + rs0;
        l1 = l1 * sc1 + rs1;
        m0 = mn0; m1 = mn1;

        #pragma unroll
        for (int nt = 0; nt < 8; nt++) {
            Oa[nt][0] *= sc0; Oa[nt][1] *= sc0;
            Oa[nt][2] *= sc1; Oa[nt][3] *= sc1;
        }

        // ---- P -> warp-private smem rows (tf32) ----
        #pragma unroll
        for (int nt = 0; nt < 8; nt++) {
            uint2 u;
            u.x = f2tf32(s[nt][0]); u.y = f2tf32(s[nt][1]);
            *(uint2*)&Ps[mrow * ASTR + nt * 8 + 2 * qq] = u;
            u.x = f2tf32(s[nt][2]); u.y = f2tf32(s[nt][3]);
            *(uint2*)&Ps[(mrow + 8) * ASTR + nt * 8 + 2 * qq] = u;
        }
        __syncwarp();

        // ---- O += P @ V ----
        #pragma unroll
        for (int kk = 0; kk < 8; kk++) {
            int kb = kk * 8;
            uint32_t af[4];
            af[0] = Ps[mrow * ASTR + kb + qq];
            af[1] = Ps[(mrow + 8) * ASTR + kb + qq];
            af[2] = Ps[mrow * ASTR + kb + qq + 4];
            af[3] = Ps[(mrow + 8) * ASTR + kb + qq + 4];
            #pragma unroll
            for (int nt = 0; nt < 8; nt++) {
                uint32_t b0 = Vs[(kb + qq) * ASTR + nt * 8 + l4];
                uint32_t b1 = Vs[(kb + qq + 4) * ASTR + nt * 8 + l4];
                asm volatile(
                    "mma.sync.aligned.m16n8k8.row.col.f32.tf32.tf32.f32 "
                    "{%0,%1,%2,%3}, {%4,%5,%6,%7}, {%8,%9}, {%0,%1,%2,%3};"
                    : "+f"(Oa[nt][0]), "+f"(Oa[nt][1]), "+f"(Oa[nt][2]), "+f"(Oa[nt][3])
                    : "r"(af[0]), "r"(af[1]), "r"(af[2]), "r"(af[3]),
                      "r"(b0), "r"(b1));
            }
        }
    }

    int b_ = bh / HEADS, h_ = bh % HEADS;
    float inv0 = 1.f / l0, inv1 = 1.f / l1;
    float* ob0 = o + ((size_t)(b_ * TT + qg0)) * EMB + h_ * 64;
    float* ob1 = o + ((size_t)(b_ * TT + qg1)) * EMB + h_ * 64;
    #pragma unroll
    for (int nt = 0; nt < 8; nt++) {
        float2 t0 = make_float2(rnd32(Oa[nt][0] * inv0), rnd32(Oa[nt][1] * inv0));
        float2 t1 = make_float2(rnd32(Oa[nt][2] * inv1), rnd32(Oa[nt][3] * inv1));
        *(float2*)&ob0[nt * 8 + 2 * qq] = t0;
        *(float2*)&ob1[nt * 8 + 2 * qq] = t1;
    }
}

// ---------------- launch ----------------
extern "C" void kernel_launch(void* const* d_in, const int* in_sizes, int n_in,
                              void* d_out, int out_size) {
    const float* x   = (const float*)d_in[0];
    const float* Wq  = (const float*)d_in[1];
    const float* Wk  = (const float*)d_in[2];
    const float* Wv  = (const float*)d_in[3];
    const float* Wp  = (const float*)d_in[4];
    const float* bp  = (const float*)d_in[5];
    const float* g1  = (const float*)d_in[6];
    const float* b1  = (const float*)d_in[7];
    const float* g2  = (const float*)d_in[8];
    const float* b2  = (const float*)d_in[9];
    const float* W1  = (const float*)d_in[10];
    const float* bf1 = (const float*)d_in[11];
    const float* W2  = (const float*)d_in[12];
    const float* bf2 = (const float*)d_in[13];
    float* out = (float*)d_out;

    float *h, *q, *k, *v, *o, *h2, *ff;
    float *wq, *wk, *wv, *wp, *w1, *w2;
    cudaGetSymbolAddress((void**)&h,  g_h);
    cudaGetSymbolAddress((void**)&q,  g_q);
    cudaGetSymbolAddress((void**)&k,  g_k);
    cudaGetSymbolAddress((void**)&v,  g_v);
    cudaGetSymbolAddress((void**)&o,  g_o);
    cudaGetSymbolAddress((void**)&h2, g_h2);
    cudaGetSymbolAddress((void**)&ff, g_ff);
    cudaGetSymbolAddress((void**)&wq, g_wq);
    cudaGetSymbolAddress((void**)&wk, g_wk);
    cudaGetSymbolAddress((void**)&wv, g_wv);
    cudaGetSymbolAddress((void**)&wp, g_wp);
    cudaGetSymbolAddress((void**)&w1, g_w1);
    cudaGetSymbolAddress((void**)&w2, g_w2);

    static bool attr_done = false;
    if (!attr_done) {
        cudaFuncSetAttribute(attn2_kernel, cudaFuncAttributeMaxDynamicSharedMemorySize,
                             (int)ATTN2_SMEM);
        cudaFuncSetAttribute(tmma_gemm<0>, cudaFuncAttributeMaxDynamicSharedMemorySize,
                             (int)GEMM_SMEM);
        cudaFuncSetAttribute(tmma_gemm<1>, cudaFuncAttributeMaxDynamicSharedMemorySize,
                             (int)GEMM_SMEM);
        cudaFuncSetAttribute(tmma_gemm<2>, cudaFuncAttributeMaxDynamicSharedMemorySize,
                             (int)GEMM_SMEM);
        attr_done = true;
    }

    // 0) weight pre-round to tf32
    {
        int nw = EMB * EMB / 4;       // 36864 float4
        int nf = EMB * DFF / 4;       // 147456 float4
        round_w_kernel<<<(nw + 255) / 256, 256>>>(Wq, wq, nw);
        round_w_kernel<<<(nw + 255) / 256, 256>>>(Wk, wk, nw);
        round_w_kernel<<<(nw + 255) / 256, 256>>>(Wv, wv, nw);
        round_w_kernel<<<(nw + 255) / 256, 256>>>(Wp, wp, nw);
        round_w_kernel<<<(nf + 255) / 256, 256>>>(W1, w1, nf);
        round_w_kernel<<<(nf + 255) / 256, 256>>>(W2, w2, nf);
    }

    // 1) ln1
    ln_kernel<<<ROWS, 128>>>(x, g1, b1, h);

    // 2) QKV projections
    {
        dim3 grid(EMB / 128, ROWS / 128);
        tmma_gemm<0><<<grid, 256, GEMM_SMEM>>>(h, wq, nullptr, nullptr, q, ROWS, EMB, EMB);
        tmma_gemm<0><<<grid, 256, GEMM_SMEM>>>(h, wk, nullptr, nullptr, k, ROWS, EMB, EMB);
        tmma_gemm<0><<<grid, 256, GEMM_SMEM>>>(h, wv, nullptr, nullptr, v, ROWS, EMB, EMB);
    }

    // 3) causal attention
    {
        dim3 grid(TT / 128, BB * HEADS);
        attn2_kernel<<<grid, 256, ATTN2_SMEM>>>(q, k, v, o);
    }

    // 4) out projection + residual -> d_out (fp32, unrounded)
    {
        dim3 grid(EMB / 128, ROWS / 128);
        tmma_gemm<1><<<grid, 256, GEMM_SMEM>>>(o, wp, bp, x, out, ROWS, EMB, EMB);
    }

    // 5) ln2
    ln_kernel<<<ROWS, 128>>>(out, g2, b2, h2);

    // 6) FF1
    {
        dim3 grid(DFF / 128, ROWS / 128);
        tmma_gemm<2><<<grid, 256, GEMM_SMEM>>>(h2, w1, bf1, nullptr, ff, ROWS, DFF, EMB);
    }

    // 7) FF2
    {
        dim3 grid(EMB / 128, ROWS / 128);
        tmma_gemm<1><<<grid, 256, GEMM_SMEM>>>(ff, w2, bf2, out, out, ROWS, EMB, DFF);
    }
}

// round 8
// speedup vs baseline: 1.6577x; 1.5506x over previous
#include <cuda_runtime.h>
#include <cuda_fp16.h>
#include <math.h>
#include <stdint.h>

#define EMB   384
#define HEADS 6
#define QD    64
#define DFF   1536
#define BB    32
#define TT    512
#define ROWS  (BB*TT)   // 16384

// ---------------- scratch (device globals; no allocation allowed) ----------------
__device__ __half g_h [ROWS*EMB];          // ln1 out (fp16)
__device__ __half g_q [ROWS*EMB];          // [B,H,T,D] fp16, pre-scaled by 1/8
__device__ __half g_k [ROWS*EMB];          // [B,H,T,D] fp16
__device__ __half g_v [ROWS*EMB];          // [B,H,D,T] fp16 (transposed!)
__device__ __half g_o [ROWS*EMB];          // attn out [B,T,C] fp16
__device__ __half g_h2[ROWS*EMB];          // ln2 out fp16
__device__ __half g_ff[ROWS*DFF];          // relu(h2@W1+b) fp16
// fp16 transposed weights: wT[n][k]
__device__ __half g_wqkv[3*EMB*EMB];       // rows 0..383=Wq^T, 384..767=Wk^T, 768..1151=Wv^T
__device__ __half g_wp [EMB*EMB];
__device__ __half g_w1t[DFF*EMB];          // [1536][384]
__device__ __half g_w2t[EMB*DFF];          // [384][1536]

__device__ __forceinline__ void cp16(uint32_t saddr, const void* gptr) {
    asm volatile("cp.async.cg.shared.global [%0], [%1], 16;"
                 :: "r"(saddr), "l"(gptr));
}

// ---------------- weight transpose + fp16 convert: dst[n][k] = half(src[k][n]) ----
__global__ void trans_w(const float* __restrict__ src, __half* __restrict__ dst,
                        int K, int N) {
    __shared__ float t[32][33];
    int n0 = blockIdx.x * 32, k0 = blockIdx.y * 32;
    int tx = threadIdx.x, ty = threadIdx.y;
    #pragma unroll
    for (int j = 0; j < 4; j++)
        t[ty + 8*j][tx] = src[(size_t)(k0 + ty + 8*j) * N + n0 + tx];
    __syncthreads();
    #pragma unroll
    for (int j = 0; j < 4; j++)
        dst[(size_t)(n0 + ty + 8*j) * K + k0 + tx] = __float2half_rn(t[tx][ty + 8*j]);
}

// ---------------- LayerNorm (fp16 output) ----------------
__global__ void ln_kernel(const float* __restrict__ x,
                          const float* __restrict__ g,
                          const float* __restrict__ b,
                          __half* __restrict__ out) {
    __shared__ float red[4];
    int row = blockIdx.x;
    int tid = threadIdx.x;
    const float* xr = x + (size_t)row * EMB;

    float v0 = xr[tid], v1 = xr[tid + 128], v2 = xr[tid + 256];
    float s = v0 + v1 + v2;
    #pragma unroll
    for (int o = 16; o; o >>= 1) s += __shfl_xor_sync(0xffffffffu, s, o);
    if ((tid & 31) == 0) red[tid >> 5] = s;
    __syncthreads();
    float mu = (red[0] + red[1] + red[2] + red[3]) * (1.0f / EMB);
    __syncthreads();

    float d0 = v0 - mu, d1 = v1 - mu, d2 = v2 - mu;
    float vv = d0*d0 + d1*d1 + d2*d2;
    #pragma unroll
    for (int o = 16; o; o >>= 1) vv += __shfl_xor_sync(0xffffffffu, vv, o);
    if ((tid & 31) == 0) red[tid >> 5] = vv;
    __syncthreads();
    float var = (red[0] + red[1] + red[2] + red[3]) * (1.0f / EMB);
    float inv = rsqrtf(var + 1e-5f);

    __half* orow = out + (size_t)row * EMB;
    orow[tid]       = __float2half_rn(d0 * inv * g[tid]       + b[tid]);
    orow[tid + 128] = __float2half_rn(d1 * inv * g[tid + 128] + b[tid + 128]);
    orow[tid + 256] = __float2half_rn(d2 * inv * g[tid + 256] + b[tid + 256]);
}

// ---------------- FP16 GEMM: C[M,N] = A[M,K] @ WT[N,K]^T ----------------
// BM=BN=128, BK=64, 256 threads (2x4 warps), warp tile 64x32, m16n8k16 fp16 mma,
// 3-stage cp.async. smem rows: 64 halves = 32 words + 4 pad -> stride 36 words.
// EPI: 0 = qkv scatter (q scaled 1/8; v transposed), 1 = +bias+residual fp32 out,
//      2 = +bias+relu fp16 out.
#define GSTR 36
#define GA_WORDS (128 * GSTR)              // 4608
#define GSTAGE_WORDS (2 * GA_WORDS)        // 9216
#define GSTAGE_BYTES (GSTAGE_WORDS * 4)    // 36864
#define GEMM_SMEM (3 * GSTAGE_BYTES)       // 110592

template<int EPI>
__global__ void __launch_bounds__(256)
hgemm(const __half* __restrict__ A, const __half* __restrict__ W,
      const float* __restrict__ bias, const float* __restrict__ R,
      void* __restrict__ Cv,
      __half* __restrict__ qO, __half* __restrict__ kO, __half* __restrict__ vO,
      int M, int N, int K) {
    extern __shared__ uint32_t smbuf[];
    uint32_t sbase = (uint32_t)__cvta_generic_to_shared(smbuf);

    int tid  = threadIdx.x;
    int lane = tid & 31;
    int warp = tid >> 5;
    int wm   = warp >> 2;
    int wn   = warp & 3;
    int l4   = lane >> 2;
    int qq   = lane & 3;
    int n0   = blockIdx.x * 128;
    int m0   = blockIdx.y * 128;

    // loaders: 128 rows x 8 chunks(16B) for each of A,B; 2 threads/row, 4 chunks each
    int row = tid >> 1;
    int cb  = (tid & 1) * 4;            // chunk base 0 or 4

    const __half* Ap = A + (size_t)(m0 + row) * K + cb * 8;
    const __half* Bp = W + (size_t)(n0 + row) * K + cb * 8;
    uint32_t sA = sbase + (row * GSTR + cb * 4) * 4;
    uint32_t sB = sbase + (GA_WORDS + row * GSTR + cb * 4) * 4;

    float acc[4][4][4];
    #pragma unroll
    for (int mt = 0; mt < 4; mt++)
        #pragma unroll
        for (int nt = 0; nt < 4; nt++)
            #pragma unroll
            for (int e = 0; e < 4; e++) acc[mt][nt][e] = 0.f;

    int nsteps = K >> 6;

    #pragma unroll
    for (int s = 0; s < 2; s++) {
        uint32_t off = s * GSTAGE_BYTES;
        int k0 = s << 6;
        #pragma unroll
        for (int i = 0; i < 4; i++) {
            cp16(sA + off + i * 16, Ap + k0 + i * 8);
            cp16(sB + off + i * 16, Bp + k0 + i * 8);
        }
        asm volatile("cp.async.commit_group;");
    }
    asm volatile("cp.async.wait_group 1;");
    __syncthreads();

    int cur = 0;
    for (int s = 0; s < nsteps; s++) {
        uint32_t* As = smbuf + cur * GSTAGE_WORDS;
        uint32_t* Bs = As + GA_WORDS;

        #pragma unroll
        for (int kk = 0; kk < 4; kk++) {       // 4 x k16
            int kb = kk * 8;
            uint32_t af[4][4], bf[4][2];
            #pragma unroll
            for (int mt = 0; mt < 4; mt++) {
                int mrow = wm * 64 + mt * 16 + l4;
                af[mt][0] = As[mrow * GSTR + kb + qq];
                af[mt][1] = As[(mrow + 8) * GSTR + kb + qq];
                af[mt][2] = As[mrow * GSTR + kb + qq + 4];
                af[mt][3] = As[(mrow + 8) * GSTR + kb + qq + 4];
            }
            #pragma unroll
            for (int nt = 0; nt < 4; nt++) {
                int nr = wn * 32 + nt * 8 + l4;
                bf[nt][0] = Bs[nr * GSTR + kb + qq];
                bf[nt][1] = Bs[nr * GSTR + kb + qq + 4];
            }
            #pragma unroll
            for (int mt = 0; mt < 4; mt++)
                #pragma unroll
                for (int nt = 0; nt < 4; nt++)
                    asm volatile(
                        "mma.sync.aligned.m16n8k16.row.col.f32.f16.f16.f32 "
                        "{%0,%1,%2,%3}, {%4,%5,%6,%7}, {%8,%9}, {%0,%1,%2,%3};"
                        : "+f"(acc[mt][nt][0]), "+f"(acc[mt][nt][1]),
                          "+f"(acc[mt][nt][2]), "+f"(acc[mt][nt][3])
                        : "r"(af[mt][0]), "r"(af[mt][1]), "r"(af[mt][2]), "r"(af[mt][3]),
                          "r"(bf[nt][0]), "r"(bf[nt][1]));
        }

        int nx = s + 2;
        if (nx < nsteps) {
            uint32_t off = (uint32_t)(nx % 3) * GSTAGE_BYTES;
            int k0 = nx << 6;
            #pragma unroll
            for (int i = 0; i < 4; i++) {
                cp16(sA + off + i * 16, Ap + k0 + i * 8);
                cp16(sB + off + i * 16, Bp + k0 + i * 8);
            }
            asm volatile("cp.async.commit_group;");
            asm volatile("cp.async.wait_group 1;");
        } else {
            asm volatile("cp.async.wait_group 0;");
        }
        __syncthreads();
        cur = (cur + 1) % 3;
    }

    // ---- epilogue ----
    #pragma unroll
    for (int mt = 0; mt < 4; mt++) {
        #pragma unroll
        for (int nt = 0; nt < 4; nt++) {
            int nb = n0 + wn * 32 + nt * 8 + qq * 2;      // even
            int mA = m0 + wm * 64 + mt * 16 + l4;
            float v0 = acc[mt][nt][0], v1 = acc[mt][nt][1];
            float v2 = acc[mt][nt][2], v3 = acc[mt][nt][3];
            if (EPI == 0) {
                int mat = nb / 384, nn = nb - mat * 384;
                int head = nn >> 6, d = nn & 63;
                int b_ = mA >> 9, tA = mA & 511;
                if (mat == 0) { v0 *= 0.125f; v1 *= 0.125f; v2 *= 0.125f; v3 *= 0.125f; }
                if (mat < 2) {
                    __half* base = mat ? kO : qO;
                    size_t off0 = ((size_t)(b_ * HEADS + head) * TT + tA) * 64 + d;
                    *(__half2*)&base[off0]            = __floats2half2_rn(v0, v1);
                    *(__half2*)&base[off0 + 8 * 64]   = __floats2half2_rn(v2, v3);
                } else {
                    size_t off0 = ((size_t)(b_ * HEADS + head) * 64 + d) * TT + tA;
                    vO[off0]            = __float2half_rn(v0);
                    vO[off0 + TT]       = __float2half_rn(v1);
                    vO[off0 + 8]        = __float2half_rn(v2);
                    vO[off0 + TT + 8]   = __float2half_rn(v3);
                }
            } else if (EPI == 1) {
                float* Cf = (float*)Cv;
                size_t o0 = (size_t)mA * N + nb;
                size_t o1 = (size_t)(mA + 8) * N + nb;
                Cf[o0]     = v0 + bias[nb]     + R[o0];
                Cf[o0 + 1] = v1 + bias[nb + 1] + R[o0 + 1];
                Cf[o1]     = v2 + bias[nb]     + R[o1];
                Cf[o1 + 1] = v3 + bias[nb + 1] + R[o1 + 1];
            } else {
                __half* Ch = (__half*)Cv;
                v0 += bias[nb];     v1 += bias[nb + 1];
                v2 += bias[nb];     v3 += bias[nb + 1];
                v0 = v0 > 0.f ? v0 : 0.f;  v1 = v1 > 0.f ? v1 : 0.f;
                v2 = v2 > 0.f ? v2 : 0.f;  v3 = v3 > 0.f ? v3 : 0.f;
                *(__half2*)&Ch[(size_t)mA * N + nb]       = __floats2half2_rn(v0, v1);
                *(__half2*)&Ch[(size_t)(mA + 8) * N + nb] = __floats2half2_rn(v2, v3);
            }
        }
    }
}

// ---------------- fp16 tensor flash attention ----------------
// q [B,H,T,64] pre-scaled; k [B,H,T,64]; v [B,H,64,T] (transposed).
// smem words: K0,K1,V0,V1 each 64*36; P 128*36.
#define ASTR 36
#define KVW (64 * ASTR)                      // 2304
#define AT_K0 0
#define AT_K1 KVW
#define AT_V0 (2 * KVW)
#define AT_V1 (3 * KVW)
#define AT_P  (4 * KVW)                      // 9216
#define ATTN_WORDS (AT_P + 128 * ASTR)       // 13824
#define ATTN_SMEM (ATTN_WORDS * 4)           // 55296

__global__ void __launch_bounds__(256)
attn3_kernel(const __half* __restrict__ q, const __half* __restrict__ k,
             const __half* __restrict__ v, __half* __restrict__ o) {
    extern __shared__ uint32_t sm2[];
    uint32_t sbase = (uint32_t)__cvta_generic_to_shared(sm2);
    uint32_t* Ps = sm2 + AT_P;

    int tid  = threadIdx.x;
    int lane = tid & 31;
    int warp = tid >> 5;
    int l4   = lane >> 2;
    int qq   = lane & 3;
    int bh   = blockIdx.y;
    int q0   = blockIdx.x * 128;

    int mrow = warp * 16 + l4;
    int qg0  = q0 + mrow;
    int qg1  = qg0 + 8;
    int ktiles = (q0 + 128) >> 6;

    // KV loaders: 64 rows x 8 chunks(16B); 4 threads/row, 2 chunks each
    int lr = tid >> 2;
    int lc = tid & 3;
    const __half* kh = k + (size_t)bh * TT * 64;
    const __half* vh = v + (size_t)bh * 64 * TT;

    // prefetch tile 0
    {
        #pragma unroll
        for (int it = 0; it < 2; it++) {
            int c = lc + it * 4;
            cp16(sbase + (AT_K0 + lr * ASTR + c * 4) * 4, kh + (size_t)lr * 64 + c * 8);
            cp16(sbase + (AT_V0 + lr * ASTR + c * 4) * 4, vh + (size_t)lr * TT + c * 8);
        }
        asm volatile("cp.async.commit_group;");
    }

    // Q fragments straight from gmem (already scaled by 1/8)
    const uint32_t* qw = (const uint32_t*)(q + (size_t)bh * TT * 64);
    uint32_t qf[4][4];
    #pragma unroll
    for (int kk = 0; kk < 4; kk++) {
        int kb = kk * 8;
        qf[kk][0] = qw[qg0 * 32 + kb + qq];
        qf[kk][1] = qw[qg1 * 32 + kb + qq];
        qf[kk][2] = qw[qg0 * 32 + kb + qq + 4];
        qf[kk][3] = qw[qg1 * 32 + kb + qq + 4];
    }

    float Oa[8][4];
    #pragma unroll
    for (int nt = 0; nt < 8; nt++)
        #pragma unroll
        for (int e = 0; e < 4; e++) Oa[nt][e] = 0.f;
    float m0 = -1e30f, m1 = -1e30f, l0 = 0.f, l1 = 0.f;

    for (int kt = 0; kt < ktiles; kt++) {
        asm volatile("cp.async.wait_group 0;");
        __syncthreads();

        if (kt + 1 < ktiles) {
            int nb = (kt + 1) & 1;
            int k0n = (kt + 1) << 6;
            uint32_t kd = (nb ? AT_K1 : AT_K0);
            uint32_t vd = (nb ? AT_V1 : AT_V0);
            #pragma unroll
            for (int it = 0; it < 2; it++) {
                int c = lc + it * 4;
                cp16(sbase + (kd + lr * ASTR + c * 4) * 4,
                     kh + (size_t)(k0n + lr) * 64 + c * 8);
                cp16(sbase + (vd + lr * ASTR + c * 4) * 4,
                     vh + (size_t)lr * TT + k0n + c * 8);
            }
            asm volatile("cp.async.commit_group;");
        }

        uint32_t* Ks = sm2 + ((kt & 1) ? AT_K1 : AT_K0);
        uint32_t* Vs = sm2 + ((kt & 1) ? AT_V1 : AT_V0);
        int k0 = kt << 6;

        // ---- S = Q @ K^T : 4 kk x 8 nt ----
        float s[8][4];
        #pragma unroll
        for (int nt = 0; nt < 8; nt++)
            #pragma unroll
            for (int e = 0; e < 4; e++) s[nt][e] = 0.f;

        #pragma unroll
        for (int kk = 0; kk < 4; kk++) {
            int kb = kk * 8;
            #pragma unroll
            for (int nt = 0; nt < 8; nt++) {
                uint32_t b0 = Ks[(nt * 8 + l4) * ASTR + kb + qq];
                uint32_t b1 = Ks[(nt * 8 + l4) * ASTR + kb + qq + 4];
                asm volatile(
                    "mma.sync.aligned.m16n8k16.row.col.f32.f16.f16.f32 "
                    "{%0,%1,%2,%3}, {%4,%5,%6,%7}, {%8,%9}, {%0,%1,%2,%3};"
                    : "+f"(s[nt][0]), "+f"(s[nt][1]), "+f"(s[nt][2]), "+f"(s[nt][3])
                    : "r"(qf[kk][0]), "r"(qf[kk][1]), "r"(qf[kk][2]), "r"(qf[kk][3]),
                      "r"(b0), "r"(b1));
            }
        }

        // ---- causal mask ----
        if (k0 + 63 > qg0) {
            #pragma unroll
            for (int nt = 0; nt < 8; nt++) {
                int kg = k0 + nt * 8 + 2 * qq;
                if (kg     > qg0) s[nt][0] = -1e30f;
                if (kg + 1 > qg0) s[nt][1] = -1e30f;
                if (kg     > qg1) s[nt][2] = -1e30f;
                if (kg + 1 > qg1) s[nt][3] = -1e30f;
            }
        }

        // ---- online softmax ----
        float r0 = -1e30f, r1 = -1e30f;
        #pragma unroll
        for (int nt = 0; nt < 8; nt++) {
            r0 = fmaxf(r0, fmaxf(s[nt][0], s[nt][1]));
            r1 = fmaxf(r1, fmaxf(s[nt][2], s[nt][3]));
        }
        r0 = fmaxf(r0, __shfl_xor_sync(0xffffffffu, r0, 1));
        r0 = fmaxf(r0, __shfl_xor_sync(0xffffffffu, r0, 2));
        r1 = fmaxf(r1, __shfl_xor_sync(0xffffffffu, r1, 1));
        r1 = fmaxf(r1, __shfl_xor_sync(0xffffffffu, r1, 2));

        float mn0 = fmaxf(m0, r0), mn1 = fmaxf(m1, r1);
        float sc0 = __expf(m0 - mn0), sc1 = __expf(m1 - mn1);
        float rs0 = 0.f, rs1 = 0.f;
        #pragma unroll
        for (int nt = 0; nt < 8; nt++) {
            s[nt][0] = __expf(s[nt][0] - mn0);
            s[nt][1] = __expf(s[nt][1] - mn0);
            s[nt][2] = __expf(s[nt][2] - mn1);
            s[nt][3] = __expf(s[nt][3] - mn1);
            rs0 += s[nt][0] + s[nt][1];
            rs1 += s[nt][2] + s[nt][3];
        }
        rs0 += __shfl_xor_sync(0xffffffffu, rs0, 1);
        rs0 += __shfl_xor_sync(0xffffffffu, rs0, 2);
        rs1 += __shfl_xor_sync(0xffffffffu, rs1, 1);
        rs1 += __shfl_xor_sync(0xffffffffu, rs1, 2);
        l0 = l0 * sc0 + rs0;
        l1 = l1 * sc1 + rs1;
        m0 = mn0; m1 = mn1;

        #pragma unroll
        for (int nt = 0; nt < 8; nt++) {
            Oa[nt][0] *= sc0; Oa[nt][1] *= sc0;
            Oa[nt][2] *= sc1; Oa[nt][3] *= sc1;
        }

        // ---- P -> warp-private smem (fp16 pairs) ----
        #pragma unroll
        for (int nt = 0; nt < 8; nt++) {
            *(__half2*)&Ps[mrow * ASTR + nt * 4 + qq]       = __floats2half2_rn(s[nt][0], s[nt][1]);
            *(__half2*)&Ps[(mrow + 8) * ASTR + nt * 4 + qq] = __floats2half2_rn(s[nt][2], s[nt][3]);
        }
        __syncwarp();

        // ---- O += P @ V : 4 kk x 8 nt ----
        #pragma unroll
        for (int kk = 0; kk < 4; kk++) {
            int kb = kk * 8;
            uint32_t af[4];
            af[0] = Ps[mrow * ASTR + kb + qq];
            af[1] = Ps[(mrow + 8) * ASTR + kb + qq];
            af[2] = Ps[mrow * ASTR + kb + qq + 4];
            af[3] = Ps[(mrow + 8) * ASTR + kb + qq + 4];
            #pragma unroll
            for (int nt = 0; nt < 8; nt++) {
                uint32_t b0 = Vs[(nt * 8 + l4) * ASTR + kb + qq];
                uint32_t b1 = Vs[(nt * 8 + l4) * ASTR + kb + qq + 4];
                asm volatile(
                    "mma.sync.aligned.m16n8k16.row.col.f32.f16.f16.f32 "
                    "{%0,%1,%2,%3}, {%4,%5,%6,%7}, {%8,%9}, {%0,%1,%2,%3};"
                    : "+f"(Oa[nt][0]), "+f"(Oa[nt][1]), "+f"(Oa[nt][2]), "+f"(Oa[nt][3])
                    : "r"(af[0]), "r"(af[1]), "r"(af[2]), "r"(af[3]),
                      "r"(b0), "r"(b1));
            }
        }
    }

    // ---- epilogue: normalize, fp16, write [B,T,C] ----
    int b_ = bh / HEADS, h_ = bh % HEADS;
    float inv0 = 1.f / l0, inv1 = 1.f / l1;
    __half* ob0 = o + ((size_t)(b_ * TT + qg0)) * EMB + h_ * 64;
    __half* ob1 = o + ((size_t)(b_ * TT + qg1)) * EMB + h_ * 64;
    #pragma unroll
    for (int nt = 0; nt < 8; nt++) {
        *(__half2*)&ob0[nt * 8 + 2 * qq] = __floats2half2_rn(Oa[nt][0] * inv0, Oa[nt][1] * inv0);
        *(__half2*)&ob1[nt * 8 + 2 * qq] = __floats2half2_rn(Oa[nt][2] * inv1, Oa[nt][3] * inv1);
    }
}

// ---------------- launch ----------------
extern "C" void kernel_launch(void* const* d_in, const int* in_sizes, int n_in,
                              void* d_out, int out_size) {
    const float* x   = (const float*)d_in[0];
    const float* Wq  = (const float*)d_in[1];
    const float* Wk  = (const float*)d_in[2];
    const float* Wv  = (const float*)d_in[3];
    const float* Wp  = (const float*)d_in[4];
    const float* bp  = (const float*)d_in[5];
    const float* g1  = (const float*)d_in[6];
    const float* b1  = (const float*)d_in[7];
    const float* g2  = (const float*)d_in[8];
    const float* b2  = (const float*)d_in[9];
    const float* W1  = (const float*)d_in[10];
    const float* bf1 = (const float*)d_in[11];
    const float* W2  = (const float*)d_in[12];
    const float* bf2 = (const float*)d_in[13];
    float* out = (float*)d_out;

    __half *h, *q, *k, *v, *o, *h2, *ff, *wqkv, *wp, *w1t, *w2t;
    cudaGetSymbolAddress((void**)&h,    g_h);
    cudaGetSymbolAddress((void**)&q,    g_q);
    cudaGetSymbolAddress((void**)&k,    g_k);
    cudaGetSymbolAddress((void**)&v,    g_v);
    cudaGetSymbolAddress((void**)&o,    g_o);
    cudaGetSymbolAddress((void**)&h2,   g_h2);
    cudaGetSymbolAddress((void**)&ff,   g_ff);
    cudaGetSymbolAddress((void**)&wqkv, g_wqkv);
    cudaGetSymbolAddress((void**)&wp,   g_wp);
    cudaGetSymbolAddress((void**)&w1t,  g_w1t);
    cudaGetSymbolAddress((void**)&w2t,  g_w2t);

    static bool attr_done = false;
    if (!attr_done) {
        cudaFuncSetAttribute(attn3_kernel, cudaFuncAttributeMaxDynamicSharedMemorySize,
                             (int)ATTN_SMEM);
        cudaFuncSetAttribute(hgemm<0>, cudaFuncAttributeMaxDynamicSharedMemorySize,
                             (int)GEMM_SMEM);
        cudaFuncSetAttribute(hgemm<1>, cudaFuncAttributeMaxDynamicSharedMemorySize,
                             (int)GEMM_SMEM);
        cudaFuncSetAttribute(hgemm<2>, cudaFuncAttributeMaxDynamicSharedMemorySize,
                             (int)GEMM_SMEM);
        attr_done = true;
    }

    // 0) weight transpose + fp16 convert
    {
        dim3 t32(32, 8);
        trans_w<<<dim3(EMB/32, EMB/32), t32>>>(Wq, wqkv,                 EMB, EMB);
        trans_w<<<dim3(EMB/32, EMB/32), t32>>>(Wk, wqkv + EMB*EMB,       EMB, EMB);
        trans_w<<<dim3(EMB/32, EMB/32), t32>>>(Wv, wqkv + 2*EMB*EMB,     EMB, EMB);
        trans_w<<<dim3(EMB/32, EMB/32), t32>>>(Wp, wp,                   EMB, EMB);
        trans_w<<<dim3(DFF/32, EMB/32), t32>>>(W1, w1t,                  EMB, DFF);
        trans_w<<<dim3(EMB/32, DFF/32), t32>>>(W2, w2t,                  DFF, EMB);
    }

    // 1) ln1 -> h (fp16)
    ln_kernel<<<ROWS, 128>>>(x, g1, b1, h);

    // 2) fused QKV projection (N=1152) with scatter epilogue
    hgemm<0><<<dim3(9, ROWS/128), 256, GEMM_SMEM>>>(
        h, wqkv, nullptr, nullptr, nullptr, q, k, v, ROWS, 3*EMB, EMB);

    // 3) causal attention
    attn3_kernel<<<dim3(TT/128, BB*HEADS), 256, ATTN_SMEM>>>(q, k, v, o);

    // 4) out projection + residual -> d_out (fp32)
    hgemm<1><<<dim3(3, ROWS/128), 256, GEMM_SMEM>>>(
        o, wp, bp, x, out, nullptr, nullptr, nullptr, ROWS, EMB, EMB);

    // 5) ln2 -> h2 (fp16)
    ln_kernel<<<ROWS, 128>>>(out, g2, b2, h2);

    // 6) FF1: relu(h2@W1+bf1) -> ff (fp16)
    hgemm<2><<<dim3(12, ROWS/128), 256, GEMM_SMEM>>>(
        h2, w1t, bf1, nullptr, ff, nullptr, nullptr, nullptr, ROWS, DFF, EMB);

    // 7) FF2: out += ff@W2 + bf2 (fp32)
    hgemm<1><<<dim3(3, ROWS/128), 256, GEMM_SMEM>>>(
        ff, w2t, bf2, out, out, nullptr, nullptr, nullptr, ROWS, EMB, DFF);
}

// round 9
// speedup vs baseline: 1.6654x; 1.0046x over previous
#include <cuda_runtime.h>
#include <cuda_fp16.h>
#include <math.h>
#include <stdint.h>

#define EMB   384
#define HEADS 6
#define QD    64
#define DFF   1536
#define BB    32
#define TT    512
#define ROWS  (BB*TT)   // 16384

// ---------------- scratch (device globals; no allocation allowed) ----------------
__device__ __half g_h [ROWS*EMB];          // ln1 out (fp16)
__device__ __half g_q [ROWS*EMB];          // [B,H,T,D] fp16, pre-scaled by 1/8
__device__ __half g_k [ROWS*EMB];          // [B,H,T,D] fp16
__device__ __half g_v [ROWS*EMB];          // [B,H,D,T] fp16 (transposed!)
__device__ __half g_o [ROWS*EMB];          // attn out [B,T,C] fp16
__device__ __half g_h2[ROWS*EMB];          // ln2 out fp16
__device__ __half g_ff[ROWS*DFF];          // relu(h2@W1+b) fp16
// fp16 transposed weights: wT[n][k]
__device__ __half g_wqkv[3*EMB*EMB];       // rows 0..383=Wq^T, 384..767=Wk^T, 768..1151=Wv^T
__device__ __half g_wp [EMB*EMB];
__device__ __half g_w1t[DFF*EMB];          // [1536][384]
__device__ __half g_w2t[EMB*DFF];          // [384][1536]

__device__ __forceinline__ void cp16(uint32_t saddr, const void* gptr) {
    asm volatile("cp.async.cg.shared.global [%0], [%1], 16;"
                 :: "r"(saddr), "l"(gptr));
}

// ---------------- weight transpose + fp16 convert: dst[n][k] = half(src[k][n]) ----
__global__ void trans_w(const float* __restrict__ src, __half* __restrict__ dst,
                        int K, int N) {
    __shared__ float t[32][33];
    int n0 = blockIdx.x * 32, k0 = blockIdx.y * 32;
    int tx = threadIdx.x, ty = threadIdx.y;
    #pragma unroll
    for (int j = 0; j < 4; j++)
        t[ty + 8*j][tx] = src[(size_t)(k0 + ty + 8*j) * N + n0 + tx];
    __syncthreads();
    #pragma unroll
    for (int j = 0; j < 4; j++)
        dst[(size_t)(n0 + ty + 8*j) * K + k0 + tx] = __float2half_rn(t[tx][ty + 8*j]);
}

// ---------------- LayerNorm (fp16 output) ----------------
__global__ void ln_kernel(const float* __restrict__ x,
                          const float* __restrict__ g,
                          const float* __restrict__ b,
                          __half* __restrict__ out) {
    __shared__ float red[4];
    int row = blockIdx.x;
    int tid = threadIdx.x;
    const float* xr = x + (size_t)row * EMB;

    float v0 = xr[tid], v1 = xr[tid + 128], v2 = xr[tid + 256];
    float s = v0 + v1 + v2;
    #pragma unroll
    for (int o = 16; o; o >>= 1) s += __shfl_xor_sync(0xffffffffu, s, o);
    if ((tid & 31) == 0) red[tid >> 5] = s;
    __syncthreads();
    float mu = (red[0] + red[1] + red[2] + red[3]) * (1.0f / EMB);
    __syncthreads();

    float d0 = v0 - mu, d1 = v1 - mu, d2 = v2 - mu;
    float vv = d0*d0 + d1*d1 + d2*d2;
    #pragma unroll
    for (int o = 16; o; o >>= 1) vv += __shfl_xor_sync(0xffffffffu, vv, o);
    if ((tid & 31) == 0) red[tid >> 5] = vv;
    __syncthreads();
    float var = (red[0] + red[1] + red[2] + red[3]) * (1.0f / EMB);
    float inv = rsqrtf(var + 1e-5f);

    __half* orow = out + (size_t)row * EMB;
    orow[tid]       = __float2half_rn(d0 * inv * g[tid]       + b[tid]);
    orow[tid + 128] = __float2half_rn(d1 * inv * g[tid + 128] + b[tid + 128]);
    orow[tid + 256] = __float2half_rn(d2 * inv * g[tid + 256] + b[tid + 256]);
}

// ---------------- FP16 GEMM: C[M,N] = A[M,K] @ WT[N,K]^T ----------------
// BM=BN=128, BK=64, 256 threads (2x4 warps), warp tile 64x32, m16n8k16 fp16 mma,
// 3-stage cp.async. smem rows: 64 halves = 32 words + 4 pad -> stride 36 words.
// EPI: 0 = qkv scatter (q scaled 1/8; v transposed), 1 = +bias+residual fp32 out,
//      2 = +bias+relu fp16 out.
#define GSTR 36
#define GA_WORDS (128 * GSTR)              // 4608
#define GSTAGE_WORDS (2 * GA_WORDS)        // 9216
#define GSTAGE_BYTES (GSTAGE_WORDS * 4)    // 36864
#define GEMM_SMEM (3 * GSTAGE_BYTES)       // 110592

template<int EPI>
__global__ void __launch_bounds__(256)
hgemm(const __half* __restrict__ A, const __half* __restrict__ W,
      const float* __restrict__ bias, const float* __restrict__ R,
      void* __restrict__ Cv,
      __half* __restrict__ qO, __half* __restrict__ kO, __half* __restrict__ vO,
      int M, int N, int K) {
    extern __shared__ uint32_t smbuf[];
    uint32_t sbase = (uint32_t)__cvta_generic_to_shared(smbuf);

    int tid  = threadIdx.x;
    int lane = tid & 31;
    int warp = tid >> 5;
    int wm   = warp >> 2;
    int wn   = warp & 3;
    int l4   = lane >> 2;
    int qq   = lane & 3;
    int n0   = blockIdx.x * 128;
    int m0   = blockIdx.y * 128;

    // loaders: 128 rows x 8 chunks(16B) for each of A,B; 2 threads/row, 4 chunks each
    int row = tid >> 1;
    int cb  = (tid & 1) * 4;            // chunk base 0 or 4

    const __half* Ap = A + (size_t)(m0 + row) * K + cb * 8;
    const __half* Bp = W + (size_t)(n0 + row) * K + cb * 8;
    uint32_t sA = sbase + (row * GSTR + cb * 4) * 4;
    uint32_t sB = sbase + (GA_WORDS + row * GSTR + cb * 4) * 4;

    float acc[4][4][4];
    #pragma unroll
    for (int mt = 0; mt < 4; mt++)
        #pragma unroll
        for (int nt = 0; nt < 4; nt++)
            #pragma unroll
            for (int e = 0; e < 4; e++) acc[mt][nt][e] = 0.f;

    int nsteps = K >> 6;

    #pragma unroll
    for (int s = 0; s < 2; s++) {
        uint32_t off = s * GSTAGE_BYTES;
        int k0 = s << 6;
        #pragma unroll
        for (int i = 0; i < 4; i++) {
            cp16(sA + off + i * 16, Ap + k0 + i * 8);
            cp16(sB + off + i * 16, Bp + k0 + i * 8);
        }
        asm volatile("cp.async.commit_group;");
    }
    asm volatile("cp.async.wait_group 1;");
    __syncthreads();

    int cur = 0;
    for (int s = 0; s < nsteps; s++) {
        uint32_t* As = smbuf + cur * GSTAGE_WORDS;
        uint32_t* Bs = As + GA_WORDS;

        #pragma unroll
        for (int kk = 0; kk < 4; kk++) {       // 4 x k16
            int kb = kk * 8;
            uint32_t af[4][4], bf[4][2];
            #pragma unroll
            for (int mt = 0; mt < 4; mt++) {
                int mrow = wm * 64 + mt * 16 + l4;
                af[mt][0] = As[mrow * GSTR + kb + qq];
                af[mt][1] = As[(mrow + 8) * GSTR + kb + qq];
                af[mt][2] = As[mrow * GSTR + kb + qq + 4];
                af[mt][3] = As[(mrow + 8) * GSTR + kb + qq + 4];
            }
            #pragma unroll
            for (int nt = 0; nt < 4; nt++) {
                int nr = wn * 32 + nt * 8 + l4;
                bf[nt][0] = Bs[nr * GSTR + kb + qq];
                bf[nt][1] = Bs[nr * GSTR + kb + qq + 4];
            }
            #pragma unroll
            for (int mt = 0; mt < 4; mt++)
                #pragma unroll
                for (int nt = 0; nt < 4; nt++)
                    asm volatile(
                        "mma.sync.aligned.m16n8k16.row.col.f32.f16.f16.f32 "
                        "{%0,%1,%2,%3}, {%4,%5,%6,%7}, {%8,%9}, {%0,%1,%2,%3};"
                        : "+f"(acc[mt][nt][0]), "+f"(acc[mt][nt][1]),
                          "+f"(acc[mt][nt][2]), "+f"(acc[mt][nt][3])
                        : "r"(af[mt][0]), "r"(af[mt][1]), "r"(af[mt][2]), "r"(af[mt][3]),
                          "r"(bf[nt][0]), "r"(bf[nt][1]));
        }

        int nx = s + 2;
        if (nx < nsteps) {
            uint32_t off = (uint32_t)(nx % 3) * GSTAGE_BYTES;
            int k0 = nx << 6;
            #pragma unroll
            for (int i = 0; i < 4; i++) {
                cp16(sA + off + i * 16, Ap + k0 + i * 8);
                cp16(sB + off + i * 16, Bp + k0 + i * 8);
            }
            asm volatile("cp.async.commit_group;");
            asm volatile("cp.async.wait_group 1;");
        } else {
            asm volatile("cp.async.wait_group 0;");
        }
        __syncthreads();
        cur = (cur + 1) % 3;
    }

    // ---- epilogue ----
    #pragma unroll
    for (int mt = 0; mt < 4; mt++) {
        #pragma unroll
        for (int nt = 0; nt < 4; nt++) {
            int nb = n0 + wn * 32 + nt * 8 + qq * 2;      // even
            int mA = m0 + wm * 64 + mt * 16 + l4;
            float v0 = acc[mt][nt][0], v1 = acc[mt][nt][1];
            float v2 = acc[mt][nt][2], v3 = acc[mt][nt][3];
            if (EPI == 0) {
                int mat = nb / 384, nn = nb - mat * 384;
                int head = nn >> 6, d = nn & 63;
                int b_ = mA >> 9, tA = mA & 511;
                if (mat == 0) { v0 *= 0.125f; v1 *= 0.125f; v2 *= 0.125f; v3 *= 0.125f; }
                if (mat < 2) {
                    __half* base = mat ? kO : qO;
                    size_t off0 = ((size_t)(b_ * HEADS + head) * TT + tA) * 64 + d;
                    *(__half2*)&base[off0]            = __floats2half2_rn(v0, v1);
                    *(__half2*)&base[off0 + 8 * 64]   = __floats2half2_rn(v2, v3);
                } else {
                    size_t off0 = ((size_t)(b_ * HEADS + head) * 64 + d) * TT + tA;
                    vO[off0]            = __float2half_rn(v0);
                    vO[off0 + TT]       = __float2half_rn(v1);
                    vO[off0 + 8]        = __float2half_rn(v2);
                    vO[off0 + TT + 8]   = __float2half_rn(v3);
                }
            } else if (EPI == 1) {
                float* Cf = (float*)Cv;
                size_t o0 = (size_t)mA * N + nb;
                size_t o1 = (size_t)(mA + 8) * N + nb;
                Cf[o0]     = v0 + bias[nb]     + R[o0];
                Cf[o0 + 1] = v1 + bias[nb + 1] + R[o0 + 1];
                Cf[o1]     = v2 + bias[nb]     + R[o1];
                Cf[o1 + 1] = v3 + bias[nb + 1] + R[o1 + 1];
            } else {
                __half* Ch = (__half*)Cv;
                v0 += bias[nb];     v1 += bias[nb + 1];
                v2 += bias[nb];     v3 += bias[nb + 1];
                v0 = v0 > 0.f ? v0 : 0.f;  v1 = v1 > 0.f ? v1 : 0.f;
                v2 = v2 > 0.f ? v2 : 0.f;  v3 = v3 > 0.f ? v3 : 0.f;
                *(__half2*)&Ch[(size_t)mA * N + nb]       = __floats2half2_rn(v0, v1);
                *(__half2*)&Ch[(size_t)(mA + 8) * N + nb] = __floats2half2_rn(v2, v3);
            }
        }
    }
}

// ---------------- fp16 tensor flash attention ----------------
// q [B,H,T,64] pre-scaled; k [B,H,T,64]; v [B,H,64,T] (transposed).
// smem words: K0,K1,V0,V1 each 64*36; P 128*36.
#define ASTR 36
#define KVW (64 * ASTR)                      // 2304
#define AT_K0 0
#define AT_K1 KVW
#define AT_V0 (2 * KVW)
#define AT_V1 (3 * KVW)
#define AT_P  (4 * KVW)                      // 9216
#define ATTN_WORDS (AT_P + 128 * ASTR)       // 13824
#define ATTN_SMEM (ATTN_WORDS * 4)           // 55296

__global__ void __launch_bounds__(256)
attn3_kernel(const __half* __restrict__ q, const __half* __restrict__ k,
             const __half* __restrict__ v, __half* __restrict__ o) {
    extern __shared__ uint32_t sm2[];
    uint32_t sbase = (uint32_t)__cvta_generic_to_shared(sm2);
    uint32_t* Ps = sm2 + AT_P;

    int tid  = threadIdx.x;
    int lane = tid & 31;
    int warp = tid >> 5;
    int l4   = lane >> 2;
    int qq   = lane & 3;
    int bh   = blockIdx.y;
    int q0   = blockIdx.x * 128;

    int mrow = warp * 16 + l4;
    int qg0  = q0 + mrow;
    int qg1  = qg0 + 8;
    int ktiles = (q0 + 128) >> 6;

    // KV loaders: 64 rows x 8 chunks(16B); 4 threads/row, 2 chunks each
    int lr = tid >> 2;
    int lc = tid & 3;
    const __half* kh = k + (size_t)bh * TT * 64;
    const __half* vh = v + (size_t)bh * 64 * TT;

    // prefetch tile 0
    {
        #pragma unroll
        for (int it = 0; it < 2; it++) {
            int c = lc + it * 4;
            cp16(sbase + (AT_K0 + lr * ASTR + c * 4) * 4, kh + (size_t)lr * 64 + c * 8);
            cp16(sbase + (AT_V0 + lr * ASTR + c * 4) * 4, vh + (size_t)lr * TT + c * 8);
        }
        asm volatile("cp.async.commit_group;");
    }

    // Q fragments straight from gmem (already scaled by 1/8)
    const uint32_t* qw = (const uint32_t*)(q + (size_t)bh * TT * 64);
    uint32_t qf[4][4];
    #pragma unroll
    for (int kk = 0; kk < 4; kk++) {
        int kb = kk * 8;
        qf[kk][0] = qw[qg0 * 32 + kb + qq];
        qf[kk][1] = qw[qg1 * 32 + kb + qq];
        qf[kk][2] = qw[qg0 * 32 + kb + qq + 4];
        qf[kk][3] = qw[qg1 * 32 + kb + qq + 4];
    }

    float Oa[8][4];
    #pragma unroll
    for (int nt = 0; nt < 8; nt++)
        #pragma unroll
        for (int e = 0; e < 4; e++) Oa[nt][e] = 0.f;
    float m0 = -1e30f, m1 = -1e30f, l0 = 0.f, l1 = 0.f;

    for (int kt = 0; kt < ktiles; kt++) {
        asm volatile("cp.async.wait_group 0;");
        __syncthreads();

        if (kt + 1 < ktiles) {
            int nb = (kt + 1) & 1;
            int k0n = (kt + 1) << 6;
            uint32_t kd = (nb ? AT_K1 : AT_K0);
            uint32_t vd = (nb ? AT_V1 : AT_V0);
            #pragma unroll
            for (int it = 0; it < 2; it++) {
                int c = lc + it * 4;
                cp16(sbase + (kd + lr * ASTR + c * 4) * 4,
                     kh + (size_t)(k0n + lr) * 64 + c * 8);
                cp16(sbase + (vd + lr * ASTR + c * 4) * 4,
                     vh + (size_t)lr * TT + k0n + c * 8);
            }
            asm volatile("cp.async.commit_group;");
        }

        uint32_t* Ks = sm2 + ((kt & 1) ? AT_K1 : AT_K0);
        uint32_t* Vs = sm2 + ((kt & 1) ? AT_V1 : AT_V0);
        int k0 = kt << 6;

        // ---- S = Q @ K^T : 4 kk x 8 nt ----
        float s[8][4];
        #pragma unroll
        for (int nt = 0; nt < 8; nt++)
            #pragma unroll
            for (int e = 0; e < 4; e++) s[nt][e] = 0.f;

        #pragma unroll
        for (int kk = 0; kk < 4; kk++) {
            int kb = kk * 8;
            #pragma unroll
            for (int nt = 0; nt < 8; nt++) {
                uint32_t b0 = Ks[(nt * 8 + l4) * ASTR + kb + qq];
                uint32_t b1 = Ks[(nt * 8 + l4) * ASTR + kb + qq + 4];
                asm volatile(
                    "mma.sync.aligned.m16n8k16.row.col.f32.f16.f16.f32 "
                    "{%0,%1,%2,%3}, {%4,%5,%6,%7}, {%8,%9}, {%0,%1,%2,%3};"
                    : "+f"(s[nt][0]), "+f"(s[nt][1]), "+f"(s[nt][2]), "+f"(s[nt][3])
                    : "r"(qf[kk][0]), "r"(qf[kk][1]), "r"(qf[kk][2]), "r"(qf[kk][3]),
                      "r"(b0), "r"(b1));
            }
        }

        // ---- causal mask ----
        if (k0 + 63 > qg0) {
            #pragma unroll
            for (int nt = 0; nt < 8; nt++) {
                int kg = k0 + nt * 8 + 2 * qq;
                if (kg     > qg0) s[nt][0] = -1e30f;
                if (kg + 1 > qg0) s[nt][1] = -1e30f;
                if (kg     > qg1) s[nt][2] = -1e30f;
                if (kg + 1 > qg1) s[nt][3] = -1e30f;
            }
        }

        // ---- online softmax ----
        float r0 = -1e30f, r1 = -1e30f;
        #pragma unroll
        for (int nt = 0; nt < 8; nt++) {
            r0 = fmaxf(r0, fmaxf(s[nt][0], s[nt][1]));
            r1 = fmaxf(r1, fmaxf(s[nt][2], s[nt][3]));
        }
        r0 = fmaxf(r0, __shfl_xor_sync(0xffffffffu, r0, 1));
        r0 = fmaxf(r0, __shfl_xor_sync(0xffffffffu, r0, 2));
        r1 = fmaxf(r1, __shfl_xor_sync(0xffffffffu, r1, 1));
        r1 = fmaxf(r1, __shfl_xor_sync(0xffffffffu, r1, 2));

        float mn0 = fmaxf(m0, r0), mn1 = fmaxf(m1, r1);
        float sc0 = __expf(m0 - mn0), sc1 = __expf(m1 - mn1);
        float rs0 = 0.f, rs1 = 0.f;
        #pragma unroll
        for (int nt = 0; nt < 8; nt++) {
            s[nt][0] = __expf(s[nt][0] - mn0);
            s[nt][1] = __expf(s[nt][1] - mn0);
            s[nt][2] = __expf(s[nt][2] - mn1);
            s[nt][3] = __expf(s[nt][3] - mn1);
            rs0 += s[nt][0] + s[nt][1];
            rs1 += s[nt][2] + s[nt][3];
        }
        rs0 += __shfl_xor_sync(0xffffffffu, rs0, 1);
        rs0 += __shfl_xor_sync(0xffffffffu, rs0, 2);
        rs1 += __shfl_xor_sync(0xffffffffu, rs1, 1);
        rs1 += __shfl_xor_sync(0xffffffffu, rs1, 2);
        l0 = l0 * sc0 + rs0;
        l1 = l1 * sc1 + rs1;
        m0 = mn0; m1 = mn1;

        #pragma unroll
        for (int nt = 0; nt < 8; nt++) {
            Oa[nt][0] *= sc0; Oa[nt][1] *= sc0;
            Oa[nt][2] *= sc1; Oa[nt][3] *= sc1;
        }

        // ---- P -> warp-private smem (fp16 pairs) ----
        #pragma unroll
        for (int nt = 0; nt < 8; nt++) {
            *(__half2*)&Ps[mrow * ASTR + nt * 4 + qq]       = __floats2half2_rn(s[nt][0], s[nt][1]);
            *(__half2*)&Ps[(mrow + 8) * ASTR + nt * 4 + qq] = __floats2half2_rn(s[nt][2], s[nt][3]);
        }
        __syncwarp();

        // ---- O += P @ V : 4 kk x 8 nt ----
        #pragma unroll
        for (int kk = 0; kk < 4; kk++) {
            int kb = kk * 8;
            uint32_t af[4];
            af[0] = Ps[mrow * ASTR + kb + qq];
            af[1] = Ps[(mrow + 8) * ASTR + kb + qq];
            af[2] = Ps[mrow * ASTR + kb + qq + 4];
            af[3] = Ps[(mrow + 8) * ASTR + kb + qq + 4];
            #pragma unroll
            for (int nt = 0; nt < 8; nt++) {
                uint32_t b0 = Vs[(nt * 8 + l4) * ASTR + kb + qq];
                uint32_t b1 = Vs[(nt * 8 + l4) * ASTR + kb + qq + 4];
                asm volatile(
                    "mma.sync.aligned.m16n8k16.row.col.f32.f16.f16.f32 "
                    "{%0,%1,%2,%3}, {%4,%5,%6,%7}, {%8,%9}, {%0,%1,%2,%3};"
                    : "+f"(Oa[nt][0]), "+f"(Oa[nt][1]), "+f"(Oa[nt][2]), "+f"(Oa[nt][3])
                    : "r"(af[0]), "r"(af[1]), "r"(af[2]), "r"(af[3]),
                      "r"(b0), "r"(b1));
            }
        }
    }

    // ---- epilogue: normalize, fp16, write [B,T,C] ----
    int b_ = bh / HEADS, h_ = bh % HEADS;
    float inv0 = 1.f / l0, inv1 = 1.f / l1;
    __half* ob0 = o + ((size_t)(b_ * TT + qg0)) * EMB + h_ * 64;
    __half* ob1 = o + ((size_t)(b_ * TT + qg1)) * EMB + h_ * 64;
    #pragma unroll
    for (int nt = 0; nt < 8; nt++) {
        *(__half2*)&ob0[nt * 8 + 2 * qq] = __floats2half2_rn(Oa[nt][0] * inv0, Oa[nt][1] * inv0);
        *(__half2*)&ob1[nt * 8 + 2 * qq] = __floats2half2_rn(Oa[nt][2] * inv1, Oa[nt][3] * inv1);
    }
}

// ---------------- launch ----------------
extern "C" void kernel_launch(void* const* d_in, const int* in_sizes, int n_in,
                              void* d_out, int out_size) {
    const float* x   = (const float*)d_in[0];
    const float* Wq  = (const float*)d_in[1];
    const float* Wk  = (const float*)d_in[2];
    const float* Wv  = (const float*)d_in[3];
    const float* Wp  = (const float*)d_in[4];
    const float* bp  = (const float*)d_in[5];
    const float* g1  = (const float*)d_in[6];
    const float* b1  = (const float*)d_in[7];
    const float* g2  = (const float*)d_in[8];
    const float* b2  = (const float*)d_in[9];
    const float* W1  = (const float*)d_in[10];
    const float* bf1 = (const float*)d_in[11];
    const float* W2  = (const float*)d_in[12];
    const float* bf2 = (const float*)d_in[13];
    float* out = (float*)d_out;

    __half *h, *q, *k, *v, *o, *h2, *ff, *wqkv, *wp, *w1t, *w2t;
    cudaGetSymbolAddress((void**)&h,    g_h);
    cudaGetSymbolAddress((void**)&q,    g_q);
    cudaGetSymbolAddress((void**)&k,    g_k);
    cudaGetSymbolAddress((void**)&v,    g_v);
    cudaGetSymbolAddress((void**)&o,    g_o);
    cudaGetSymbolAddress((void**)&h2,   g_h2);
    cudaGetSymbolAddress((void**)&ff,   g_ff);
    cudaGetSymbolAddress((void**)&wqkv, g_wqkv);
    cudaGetSymbolAddress((void**)&wp,   g_wp);
    cudaGetSymbolAddress((void**)&w1t,  g_w1t);
    cudaGetSymbolAddress((void**)&w2t,  g_w2t);

    static bool attr_done = false;
    if (!attr_done) {
        cudaFuncSetAttribute(attn3_kernel, cudaFuncAttributeMaxDynamicSharedMemorySize,
                             (int)ATTN_SMEM);
        cudaFuncSetAttribute(hgemm<0>, cudaFuncAttributeMaxDynamicSharedMemorySize,
                             (int)GEMM_SMEM);
        cudaFuncSetAttribute(hgemm<1>, cudaFuncAttributeMaxDynamicSharedMemorySize,
                             (int)GEMM_SMEM);
        cudaFuncSetAttribute(hgemm<2>, cudaFuncAttributeMaxDynamicSharedMemorySize,
                             (int)GEMM_SMEM);
        attr_done = true;
    }

    // 0) weight transpose + fp16 convert
    {
        dim3 t32(32, 8);
        trans_w<<<dim3(EMB/32, EMB/32), t32>>>(Wq, wqkv,                 EMB, EMB);
        trans_w<<<dim3(EMB/32, EMB/32), t32>>>(Wk, wqkv + EMB*EMB,       EMB, EMB);
        trans_w<<<dim3(EMB/32, EMB/32), t32>>>(Wv, wqkv + 2*EMB*EMB,     EMB, EMB);
        trans_w<<<dim3(EMB/32, EMB/32), t32>>>(Wp, wp,                   EMB, EMB);
        trans_w<<<dim3(DFF/32, EMB/32), t32>>>(W1, w1t,                  EMB, DFF);
        trans_w<<<dim3(EMB/32, DFF/32), t32>>>(W2, w2t,                  DFF, EMB);
    }

    // 1) ln1 -> h (fp16)
    ln_kernel<<<ROWS, 128>>>(x, g1, b1, h);

    // 2) fused QKV projection (N=1152) with scatter epilogue
    hgemm<0><<<dim3(9, ROWS/128), 256, GEMM_SMEM>>>(
        h, wqkv, nullptr, nullptr, nullptr, q, k, v, ROWS, 3*EMB, EMB);

    // 3) causal attention
    attn3_kernel<<<dim3(TT/128, BB*HEADS), 256, ATTN_SMEM>>>(q, k, v, o);

    // 4) out projection + residual -> d_out (fp32)
    hgemm<1><<<dim3(3, ROWS/128), 256, GEMM_SMEM>>>(
        o, wp, bp, x, out, nullptr, nullptr, nullptr, ROWS, EMB, EMB);

    // 5) ln2 -> h2 (fp16)
    ln_kernel<<<ROWS, 128>>>(out, g2, b2, h2);

    // 6) FF1: relu(h2@W1+bf1) -> ff (fp16)
    hgemm<2><<<dim3(12, ROWS/128), 256, GEMM_SMEM>>>(
        h2, w1t, bf1, nullptr, ff, nullptr, nullptr, nullptr, ROWS, DFF, EMB);

    // 7) FF2: out += ff@W2 + bf2 (fp32)
    hgemm<1><<<dim3(3, ROWS/128), 256, GEMM_SMEM>>>(
        ff, w2t, bf2, out, out, nullptr, nullptr, nullptr, ROWS, EMB, DFF);
}

// round 11
// speedup vs baseline: 2.3523x; 1.4125x over previous
#include <cuda_runtime.h>
#include <cuda_fp16.h>
#include <stdint.h>

#define EMB   384
#define HEADS 6
#define DFF   1536
#define BB    32
#define TT    512
#define ROWS  (BB*TT)

// Chunked-SW128 layout: 16KB blocks of [128 rows][64 halves];
// block = (row>>7)*(K/64) + (k>>6); byte = sw128((row&127)*128 + (k&63)*2)
__device__ __half g_h [ROWS*EMB];     // ln1 out, chunked K=384
__device__ __half g_q [ROWS*EMB];     // [B,H,T,D] linear, pre-scaled 1/8
__device__ __half g_k [ROWS*EMB];     // [B,H,T,D] linear
__device__ __half g_v [ROWS*EMB];     // [B,H,D,T] linear (transposed)
__device__ __half g_o [ROWS*EMB];     // attn out, chunked K=384
__device__ __half g_h2[ROWS*EMB];     // ln2 out, chunked K=384
__device__ __half g_ff[ROWS*DFF];     // ff1 out, chunked K=1536
__device__ __half g_wqkv[3*EMB*EMB];  // B-chunked (n-major blocks)
__device__ __half g_wp [EMB*EMB];
__device__ __half g_w1t[DFF*EMB];
__device__ __half g_w2t[EMB*DFF];

__device__ __forceinline__ void cp16(uint32_t saddr, const void* gptr) {
    asm volatile("cp.async.cg.shared.global [%0], [%1], 16;" :: "r"(saddr), "l"(gptr));
}
__device__ __forceinline__ uint32_t sw128(uint32_t off) {
    return off ^ ((off >> 3) & 0x70);
}
__device__ __forceinline__ void mwait(uint32_t mbar, uint32_t parity) {
    asm volatile(
        "{\n\t.reg .pred P;\n\tMW%=:\n\t"
        "mbarrier.try_wait.parity.acquire.cta.shared::cta.b64 P, [%0], %1;\n\t"
        "@!P bra MW%=;\n\t}" :: "r"(mbar), "r"(parity) : "memory");
}
__device__ __forceinline__ void bulk_ld(uint32_t saddr, const void* g, uint32_t bytes,
                                        uint32_t mbar) {
    asm volatile("cp.async.bulk.shared::cluster.global.mbarrier::complete_tx::bytes "
                 "[%0], [%1], %2, [%3];"
                 :: "r"(saddr), "l"(g), "r"(bytes), "r"(mbar) : "memory");
}

// ---- fused weight transpose + fp16 + chunked swizzle ----
__global__ void trans_all(const float* Wq, const float* Wk, const float* Wv,
                          const float* Wp, const float* W1, const float* W2,
                          __half* wqkv, __half* wp, __half* w1t, __half* w2t) {
    __shared__ float t[32][33];
    int id = blockIdx.x;
    const float* src; __half* dst; int K, N;
    if (id < 576) {
        int w = id / 144; id -= w * 144;
        src = (w == 0) ? Wq : (w == 1) ? Wk : (w == 2) ? Wv : Wp;
        dst = (w < 3) ? (wqkv + (size_t)w * EMB * EMB) : wp;
        K = 384; N = 384;
    } else if (id < 1152) { id -= 576;  src = W1; dst = w1t; K = 384;  N = 1536; }
    else                  { id -= 1152; src = W2; dst = w2t; K = 1536; N = 384;  }
    int ntn = N / 32;
    int n0 = (id % ntn) * 32, k0 = (id / ntn) * 32;
    int tx = threadIdx.x, ty = threadIdx.y;
    #pragma unroll
    for (int j = 0; j < 4; j++)
        t[ty + 8*j][tx] = src[(size_t)(k0 + ty + 8*j) * N + n0 + tx];
    __syncthreads();
    int KB = K >> 6;
    #pragma unroll
    for (int j = 0; j < 4; j++) {
        int n = n0 + ty + 8*j, k = k0 + tx;
        int blk = (n >> 7) * KB + (k >> 6);
        uint32_t bo = sw128((uint32_t)(n & 127) * 128 + (uint32_t)(k & 63) * 2);
        *(__half*)((char*)dst + (size_t)blk * 16384 + bo) = __float2half_rn(t[tx][ty + 8*j]);
    }
}

// ---- LayerNorm -> chunked fp16 (K=384) ----
__global__ void ln_kernel(const float* __restrict__ x, const float* __restrict__ g,
                          const float* __restrict__ b, __half* __restrict__ out) {
    __shared__ float red[4];
    int row = blockIdx.x, tid = threadIdx.x;
    const float* xr = x + (size_t)row * EMB;
    float v0 = xr[tid], v1 = xr[tid + 128], v2 = xr[tid + 256];
    float s = v0 + v1 + v2;
    #pragma unroll
    for (int o = 16; o; o >>= 1) s += __shfl_xor_sync(0xffffffffu, s, o);
    if ((tid & 31) == 0) red[tid >> 5] = s;
    __syncthreads();
    float mu = (red[0] + red[1] + red[2] + red[3]) * (1.0f / EMB);
    __syncthreads();
    float d0 = v0 - mu, d1 = v1 - mu, d2 = v2 - mu;
    float vv = d0*d0 + d1*d1 + d2*d2;
    #pragma unroll
    for (int o = 16; o; o >>= 1) vv += __shfl_xor_sync(0xffffffffu, vv, o);
    if ((tid & 31) == 0) red[tid >> 5] = vv;
    __syncthreads();
    float var = (red[0] + red[1] + red[2] + red[3]) * (1.0f / EMB);
    float inv = rsqrtf(var + 1e-5f);
    char* ob = (char*)out;
    uint32_t rb = (uint32_t)(row & 127) * 128;
    int mb6 = (row >> 7) * 6;
    #pragma unroll
    for (int j = 0; j < 3; j++) {
        int k = tid + j * 128;
        float dv = (j == 0) ? d0 : (j == 1) ? d1 : d2;
        float val = dv * inv * g[k] + b[k];
        uint32_t bo = sw128(rb + (uint32_t)(k & 63) * 2);
        *(__half*)(ob + (size_t)(mb6 + (k >> 6)) * 16384 + bo) = __float2half_rn(val);
    }
}

// ---- FP16 warp-MMA GEMM with bulk-copy loads ----
// BM=BN=128, BK=64 chunk, 256 threads (2x4 warps, warp tile 64x32),
// 3-stage pipeline: 2 cp.async.bulk per chunk + mbarrier expect_tx.
#define HG_HDR 1024
#define HG_BUF 16384
#define HG_STAGE (2 * HG_BUF)
#define HG_SMEM (HG_HDR + 3 * HG_STAGE)   // 99328

template<int EPI>
__global__ void __launch_bounds__(256)
hgemm(const __half* __restrict__ A, const __half* __restrict__ W,
      const float* __restrict__ bias, const float* __restrict__ R,
      void* __restrict__ Cv, __half* qO, __half* kO, __half* vO, int N, int K) {
    extern __shared__ char smem[];
    uint32_t sb = (uint32_t)__cvta_generic_to_shared(smem);
    int tid  = threadIdx.x;
    int lane = tid & 31, warp = tid >> 5;
    int wm = warp >> 2, wn = warp & 3;
    int l4 = lane >> 2, qq = lane & 3;
    int n0 = blockIdx.x * 128, m0 = blockIdx.y * 128;
    int KB = K >> 6;
    int mbA = blockIdx.y, nbB = blockIdx.x;
    const char* Ab = (const char*)A;
    const char* Wb = (const char*)W;

    if (tid < 3)
        asm volatile("mbarrier.init.shared.b64 [%0], 1;" :: "r"(sb + tid * 8) : "memory");
    __syncthreads();

    auto load = [&](int c) {
        int st = c % 3;
        uint32_t mb = sb + st * 8;
        uint32_t d  = sb + HG_HDR + (uint32_t)st * HG_STAGE;
        asm volatile("mbarrier.arrive.expect_tx.shared.b64 _, [%0], %1;"
                     :: "r"(mb), "r"((uint32_t)HG_STAGE) : "memory");
        bulk_ld(d,          Ab + (size_t)(mbA * KB + c) * HG_BUF, HG_BUF, mb);
        bulk_ld(d + HG_BUF, Wb + (size_t)(nbB * KB + c) * HG_BUF, HG_BUF, mb);
    };
    if (tid == 0) { load(0); load(1); }

    float acc[4][4][4];
    #pragma unroll
    for (int mt = 0; mt < 4; mt++)
        #pragma unroll
        for (int nt = 0; nt < 4; nt++)
            #pragma unroll
            for (int e = 0; e < 4; e++) acc[mt][nt][e] = 0.f;

    for (int c = 0; c < KB; c++) {
        int st = c % 3;
        mwait(sb + st * 8, (uint32_t)((c / 3) & 1));
        const char* As = smem + HG_HDR + (size_t)st * HG_STAGE;
        const char* Bs = As + HG_BUF;

        #pragma unroll
        for (int kk = 0; kk < 4; kk++) {
            int kb = kk * 8;
            uint32_t af[4][4], bf[4][2];
            #pragma unroll
            for (int mt = 0; mt < 4; mt++) {
                int mr = wm * 64 + mt * 16 + l4;
                af[mt][0] = *(const uint32_t*)(As + sw128((uint32_t)mr * 128 + (kb + qq) * 4));
                af[mt][1] = *(const uint32_t*)(As + sw128((uint32_t)(mr + 8) * 128 + (kb + qq) * 4));
                af[mt][2] = *(const uint32_t*)(As + sw128((uint32_t)mr * 128 + (kb + qq + 4) * 4));
                af[mt][3] = *(const uint32_t*)(As + sw128((uint32_t)(mr + 8) * 128 + (kb + qq + 4) * 4));
            }
            #pragma unroll
            for (int nt = 0; nt < 4; nt++) {
                int nr = wn * 32 + nt * 8 + l4;
                bf[nt][0] = *(const uint32_t*)(Bs + sw128((uint32_t)nr * 128 + (kb + qq) * 4));
                bf[nt][1] = *(const uint32_t*)(Bs + sw128((uint32_t)nr * 128 + (kb + qq + 4) * 4));
            }
            #pragma unroll
            for (int mt = 0; mt < 4; mt++)
                #pragma unroll
                for (int nt = 0; nt < 4; nt++)
                    asm volatile(
                        "mma.sync.aligned.m16n8k16.row.col.f32.f16.f16.f32 "
                        "{%0,%1,%2,%3}, {%4,%5,%6,%7}, {%8,%9}, {%0,%1,%2,%3};"
                        : "+f"(acc[mt][nt][0]), "+f"(acc[mt][nt][1]),
                          "+f"(acc[mt][nt][2]), "+f"(acc[mt][nt][3])
                        : "r"(af[mt][0]), "r"(af[mt][1]), "r"(af[mt][2]), "r"(af[mt][3]),
                          "r"(bf[nt][0]), "r"(bf[nt][1]));
        }
        __syncthreads();                      // all warps done with buffer (c-1)%3 and c
        if (c + 2 < KB && tid == 0) load(c + 2);
    }

    // ---- epilogue (R8) ----
    #pragma unroll
    for (int mt = 0; mt < 4; mt++) {
        #pragma unroll
        for (int nt = 0; nt < 4; nt++) {
            int nb = n0 + wn * 32 + nt * 8 + qq * 2;
            int mA = m0 + wm * 64 + mt * 16 + l4;
            float v0 = acc[mt][nt][0], v1 = acc[mt][nt][1];
            float v2 = acc[mt][nt][2], v3 = acc[mt][nt][3];
            if (EPI == 0) {
                int mat = nb / 384, nn = nb - mat * 384;
                int head = nn >> 6, d = nn & 63;
                int b_ = mA >> 9, tA = mA & 511;
                if (mat == 0) { v0 *= 0.125f; v1 *= 0.125f; v2 *= 0.125f; v3 *= 0.125f; }
                if (mat < 2) {
                    __half* base = mat ? kO : qO;
                    size_t off0 = ((size_t)(b_ * HEADS + head) * TT + tA) * 64 + d;
                    *(__half2*)&base[off0]          = __floats2half2_rn(v0, v1);
                    *(__half2*)&base[off0 + 8 * 64] = __floats2half2_rn(v2, v3);
                } else {
                    size_t off0 = ((size_t)(b_ * HEADS + head) * 64 + d) * TT + tA;
                    vO[off0]          = __float2half_rn(v0);
                    vO[off0 + TT]     = __float2half_rn(v1);
                    vO[off0 + 8]      = __float2half_rn(v2);
                    vO[off0 + TT + 8] = __float2half_rn(v3);
                }
            } else if (EPI == 1) {
                float* Cf = (float*)Cv;
                size_t o0 = (size_t)mA * N + nb;
                size_t o1 = (size_t)(mA + 8) * N + nb;
                Cf[o0]     = v0 + bias[nb]     + R[o0];
                Cf[o0 + 1] = v1 + bias[nb + 1] + R[o0 + 1];
                Cf[o1]     = v2 + bias[nb]     + R[o1];
                Cf[o1 + 1] = v3 + bias[nb + 1] + R[o1 + 1];
            } else {
                // relu -> chunked fp16 (A operand of FF2, K=N here)
                char* Ch = (char*)Cv;
                v0 += bias[nb];     v1 += bias[nb + 1];
                v2 += bias[nb];     v3 += bias[nb + 1];
                v0 = v0 > 0.f ? v0 : 0.f;  v1 = v1 > 0.f ? v1 : 0.f;
                v2 = v2 > 0.f ? v2 : 0.f;  v3 = v3 > 0.f ? v3 : 0.f;
                int blk = (mA >> 7) * (N >> 6) + (nb >> 6);
                uint32_t b0 = sw128((uint32_t)(mA & 127) * 128 + (uint32_t)(nb & 63) * 2);
                uint32_t b1 = sw128((uint32_t)((mA + 8) & 127) * 128 + (uint32_t)(nb & 63) * 2);
                *(__half2*)(Ch + (size_t)blk * 16384 + b0) = __floats2half2_rn(v0, v1);
                *(__half2*)(Ch + (size_t)blk * 16384 + b1) = __floats2half2_rn(v2, v3);
            }
        }
    }
}

// ---- fp16 flash attention (R8 core; o written chunked) ----
#define ASTR 36
#define KVW (64 * ASTR)
#define AT_K0 0
#define AT_K1 KVW
#define AT_V0 (2 * KVW)
#define AT_V1 (3 * KVW)
#define AT_P  (4 * KVW)
#define ATTN_SMEM ((AT_P + 128 * ASTR) * 4)

__global__ void __launch_bounds__(256)
attn3_kernel(const __half* __restrict__ q, const __half* __restrict__ k,
             const __half* __restrict__ v, __half* __restrict__ o) {
    extern __shared__ uint32_t sm2[];
    uint32_t sbase = (uint32_t)__cvta_generic_to_shared(sm2);
    uint32_t* Ps = sm2 + AT_P;
    int tid = threadIdx.x, lane = tid & 31, warp = tid >> 5;
    int l4 = lane >> 2, qq = lane & 3;
    int bh = blockIdx.y, q0 = blockIdx.x * 128;
    int mrow = warp * 16 + l4, qg0 = q0 + mrow, qg1 = qg0 + 8;
    int ktiles = (q0 + 128) >> 6;
    int lr = tid >> 2, lc = tid & 3;
    const __half* kh = k + (size_t)bh * TT * 64;
    const __half* vh = v + (size_t)bh * 64 * TT;

    #pragma unroll
    for (int it = 0; it < 2; it++) {
        int c = lc + it * 4;
        cp16(sbase + (AT_K0 + lr * ASTR + c * 4) * 4, kh + (size_t)lr * 64 + c * 8);
        cp16(sbase + (AT_V0 + lr * ASTR + c * 4) * 4, vh + (size_t)lr * TT + c * 8);
    }
    asm volatile("cp.async.commit_group;");

    const uint32_t* qw = (const uint32_t*)(q + (size_t)bh * TT * 64);
    uint32_t qf[4][4];
    #pragma unroll
    for (int kk = 0; kk < 4; kk++) {
        int kb = kk * 8;
        qf[kk][0] = qw[qg0 * 32 + kb + qq];
        qf[kk][1] = qw[qg1 * 32 + kb + qq];
        qf[kk][2] = qw[qg0 * 32 + kb + qq + 4];
        qf[kk][3] = qw[qg1 * 32 + kb + qq + 4];
    }

    float Oa[8][4];
    #pragma unroll
    for (int nt = 0; nt < 8; nt++)
        #pragma unroll
        for (int e = 0; e < 4; e++) Oa[nt][e] = 0.f;
    float m0 = -1e30f, m1 = -1e30f, l0 = 0.f, l1 = 0.f;

    for (int kt = 0; kt < ktiles; kt++) {
        asm volatile("cp.async.wait_group 0;");
        __syncthreads();
        if (kt + 1 < ktiles) {
            int nb = (kt + 1) & 1, k0n = (kt + 1) << 6;
            uint32_t kd = (nb ? AT_K1 : AT_K0), vd = (nb ? AT_V1 : AT_V0);
            #pragma unroll
            for (int it = 0; it < 2; it++) {
                int c = lc + it * 4;
                cp16(sbase + (kd + lr * ASTR + c * 4) * 4, kh + (size_t)(k0n + lr) * 64 + c * 8);
                cp16(sbase + (vd + lr * ASTR + c * 4) * 4, vh + (size_t)lr * TT + k0n + c * 8);
            }
            asm volatile("cp.async.commit_group;");
        }
        uint32_t* Ks = sm2 + ((kt & 1) ? AT_K1 : AT_K0);
        uint32_t* Vs = sm2 + ((kt & 1) ? AT_V1 : AT_V0);
        int k0 = kt << 6;

        float s[8][4];
        #pragma unroll
        for (int nt = 0; nt < 8; nt++)
            #pragma unroll
            for (int e = 0; e < 4; e++) s[nt][e] = 0.f;
        #pragma unroll
        for (int kk = 0; kk < 4; kk++) {
            int kb = kk * 8;
            #pragma unroll
            for (int nt = 0; nt < 8; nt++) {
                uint32_t b0 = Ks[(nt * 8 + l4) * ASTR + kb + qq];
                uint32_t b1 = Ks[(nt * 8 + l4) * ASTR + kb + qq + 4];
                asm volatile(
                    "mma.sync.aligned.m16n8k16.row.col.f32.f16.f16.f32 "
                    "{%0,%1,%2,%3}, {%4,%5,%6,%7}, {%8,%9}, {%0,%1,%2,%3};"
                    : "+f"(s[nt][0]), "+f"(s[nt][1]), "+f"(s[nt][2]), "+f"(s[nt][3])
                    : "r"(qf[kk][0]), "r"(qf[kk][1]), "r"(qf[kk][2]), "r"(qf[kk][3]),
                      "r"(b0), "r"(b1));
            }
        }
        if (k0 + 63 > qg0) {
            #pragma unroll
            for (int nt = 0; nt < 8; nt++) {
                int kg = k0 + nt * 8 + 2 * qq;
                if (kg     > qg0) s[nt][0] = -1e30f;
                if (kg + 1 > qg0) s[nt][1] = -1e30f;
                if (kg     > qg1) s[nt][2] = -1e30f;
                if (kg + 1 > qg1) s[nt][3] = -1e30f;
            }
        }
        float r0 = -1e30f, r1 = -1e30f;
        #pragma unroll
        for (int nt = 0; nt < 8; nt++) {
            r0 = fmaxf(r0, fmaxf(s[nt][0], s[nt][1]));
            r1 = fmaxf(r1, fmaxf(s[nt][2], s[nt][3]));
        }
        r0 = fmaxf(r0, __shfl_xor_sync(0xffffffffu, r0, 1));
        r0 = fmaxf(r0, __shfl_xor_sync(0xffffffffu, r0, 2));
        r1 = fmaxf(r1, __shfl_xor_sync(0xffffffffu, r1, 1));
        r1 = fmaxf(r1, __shfl_xor_sync(0xffffffffu, r1, 2));
        float mn0 = fmaxf(m0, r0), mn1 = fmaxf(m1, r1);
        float sc0 = __expf(m0 - mn0), sc1 = __expf(m1 - mn1);
        float rs0 = 0.f, rs1 = 0.f;
        #pragma unroll
        for (int nt = 0; nt < 8; nt++) {
            s[nt][0] = __expf(s[nt][0] - mn0);
            s[nt][1] = __expf(s[nt][1] - mn0);
            s[nt][2] = __expf(s[nt][2] - mn1);
            s[nt][3] = __expf(s[nt][3] - mn1);
            rs0 += s[nt][0] + s[nt][1];
            rs1 += s[nt][2] + s[nt][3];
        }
        rs0 += __shfl_xor_sync(0xffffffffu, rs0, 1);
        rs0 += __shfl_xor_sync(0xffffffffu, rs0, 2);
        rs1 += __shfl_xor_sync(0xffffffffu, rs1, 1);
        rs1 += __shfl_xor_sync(0xffffffffu, rs1, 2);
        l0 = l0 * sc0 + rs0;  l1 = l1 * sc1 + rs1;
        m0 = mn0;  m1 = mn1;
        #pragma unroll
        for (int nt = 0; nt < 8; nt++) {
            Oa[nt][0] *= sc0; Oa[nt][1] *= sc0;
            Oa[nt][2] *= sc1; Oa[nt][3] *= sc1;
        }
        #pragma unroll
        for (int nt = 0; nt < 8; nt++) {
            *(__half2*)&Ps[mrow * ASTR + nt * 4 + qq]       = __floats2half2_rn(s[nt][0], s[nt][1]);
            *(__half2*)&Ps[(mrow + 8) * ASTR + nt * 4 + qq] = __floats2half2_rn(s[nt][2], s[nt][3]);
        }
        __syncwarp();
        #pragma unroll
        for (int kk = 0; kk < 4; kk++) {
            int kb = kk * 8;
            uint32_t af[4];
            af[0] = Ps[mrow * ASTR + kb + qq];
            af[1] = Ps[(mrow + 8) * ASTR + kb + qq];
            af[2] = Ps[mrow * ASTR + kb + qq + 4];
            af[3] = Ps[(mrow + 8) * ASTR + kb + qq + 4];
            #pragma unroll
            for (int nt = 0; nt < 8; nt++) {
                uint32_t b0 = Vs[(nt * 8 + l4) * ASTR + kb + qq];
                uint32_t b1 = Vs[(nt * 8 + l4) * ASTR + kb + qq + 4];
                asm volatile(
                    "mma.sync.aligned.m16n8k16.row.col.f32.f16.f16.f32 "
                    "{%0,%1,%2,%3}, {%4,%5,%6,%7}, {%8,%9}, {%0,%1,%2,%3};"
                    : "+f"(Oa[nt][0]), "+f"(Oa[nt][1]), "+f"(Oa[nt][2]), "+f"(Oa[nt][3])
                    : "r"(af[0]), "r"(af[1]), "r"(af[2]), "r"(af[3]), "r"(b0), "r"(b1));
            }
        }
    }

    int b_ = bh / HEADS, h_ = bh % HEADS;
    float inv0 = 1.f / l0, inv1 = 1.f / l1;
    char* ob = (char*)o;
    int row0 = b_ * TT + qg0, row1 = b_ * TT + qg1;
    size_t blk0 = (size_t)((row0 >> 7) * 6 + h_) * 16384;
    size_t blk1 = (size_t)((row1 >> 7) * 6 + h_) * 16384;
    uint32_t rb0 = (uint32_t)(row0 & 127) * 128, rb1 = (uint32_t)(row1 & 127) * 128;
    #pragma unroll
    for (int nt = 0; nt < 8; nt++) {
        uint32_t co = (uint32_t)(nt * 8 + 2 * qq) * 2;
        *(__half2*)(ob + blk0 + sw128(rb0 + co)) = __floats2half2_rn(Oa[nt][0] * inv0, Oa[nt][1] * inv0);
        *(__half2*)(ob + blk1 + sw128(rb1 + co)) = __floats2half2_rn(Oa[nt][2] * inv1, Oa[nt][3] * inv1);
    }
}

// ---------------- launch ----------------
extern "C" void kernel_launch(void* const* d_in, const int* in_sizes, int n_in,
                              void* d_out, int out_size) {
    const float* x   = (const float*)d_in[0];
    const float* Wq  = (const float*)d_in[1];
    const float* Wk  = (const float*)d_in[2];
    const float* Wv  = (const float*)d_in[3];
    const float* Wp  = (const float*)d_in[4];
    const float* bp  = (const float*)d_in[5];
    const float* g1  = (const float*)d_in[6];
    const float* b1  = (const float*)d_in[7];
    const float* g2  = (const float*)d_in[8];
    const float* b2  = (const float*)d_in[9];
    const float* W1  = (const float*)d_in[10];
    const float* bf1 = (const float*)d_in[11];
    const float* W2  = (const float*)d_in[12];
    const float* bf2 = (const float*)d_in[13];
    float* out = (float*)d_out;

    __half *h, *q, *k, *v, *o, *h2, *ff, *wqkv, *wp, *w1t, *w2t;
    cudaGetSymbolAddress((void**)&h,    g_h);
    cudaGetSymbolAddress((void**)&q,    g_q);
    cudaGetSymbolAddress((void**)&k,    g_k);
    cudaGetSymbolAddress((void**)&v,    g_v);
    cudaGetSymbolAddress((void**)&o,    g_o);
    cudaGetSymbolAddress((void**)&h2,   g_h2);
    cudaGetSymbolAddress((void**)&ff,   g_ff);
    cudaGetSymbolAddress((void**)&wqkv, g_wqkv);
    cudaGetSymbolAddress((void**)&wp,   g_wp);
    cudaGetSymbolAddress((void**)&w1t,  g_w1t);
    cudaGetSymbolAddress((void**)&w2t,  g_w2t);

    static bool attr_done = false;
    if (!attr_done) {
        cudaFuncSetAttribute(attn3_kernel, cudaFuncAttributeMaxDynamicSharedMemorySize, (int)ATTN_SMEM);
        cudaFuncSetAttribute(hgemm<0>, cudaFuncAttributeMaxDynamicSharedMemorySize, (int)HG_SMEM);
        cudaFuncSetAttribute(hgemm<1>, cudaFuncAttributeMaxDynamicSharedMemorySize, (int)HG_SMEM);
        cudaFuncSetAttribute(hgemm<2>, cudaFuncAttributeMaxDynamicSharedMemorySize, (int)HG_SMEM);
        attr_done = true;
    }

    trans_all<<<1728, dim3(32, 8)>>>(Wq, Wk, Wv, Wp, W1, W2, wqkv, wp, w1t, w2t);
    ln_kernel<<<ROWS, 128>>>(x, g1, b1, h);
    // QKV: N=1152, K=384
    hgemm<0><<<dim3(9, ROWS/128), 256, HG_SMEM>>>(h, wqkv, nullptr, nullptr, nullptr, q, k, v, 1152, 384);
    attn3_kernel<<<dim3(TT/128, BB*HEADS), 256, ATTN_SMEM>>>(q, k, v, o);
    // out proj + residual (fp32): N=384, K=384
    hgemm<1><<<dim3(3, ROWS/128), 256, HG_SMEM>>>(o, wp, bp, x, out, nullptr, nullptr, nullptr, 384, 384);
    ln_kernel<<<ROWS, 128>>>(out, g2, b2, h2);
    // FF1 relu -> chunked: N=1536, K=384
    hgemm<2><<<dim3(12, ROWS/128), 256, HG_SMEM>>>(h2, w1t, bf1, nullptr, ff, nullptr, nullptr, nullptr, 1536, 384);
    // FF2 + residual (fp32): N=384, K=1536
    hgemm<1><<<dim3(3, ROWS/128), 256, HG_SMEM>>>(ff, w2t, bf2, out, out, nullptr, nullptr, nullptr, 384, 1536);
}

// round 13
// speedup vs baseline: 2.4074x; 1.0234x over previous
#include <cuda_runtime.h>
#include <cuda_fp16.h>
#include <stdint.h>

#define EMB   384
#define HEADS 6
#define DFF   1536
#define BB    32
#define TT    512
#define ROWS  (BB*TT)

// Chunked-SW128 layout: 16KB blocks of [128 rows][64 halves];
// block = (row>>7)*(K/64) + (k>>6); byte = sw128((row&127)*128 + (k&63)*2)
__device__ __half g_h [ROWS*EMB];     // ln1 out, chunked K=384
__device__ __half g_q [ROWS*EMB];     // [B,H,T,D] linear, pre-scaled 1/8
__device__ __half g_k [ROWS*EMB];     // [B,H,T,D] linear
__device__ __half g_v [ROWS*EMB];     // [B,H,D,T] linear (transposed)
__device__ __half g_o [ROWS*EMB];     // attn out, chunked K=384
__device__ __half g_h2[ROWS*EMB];     // ln2 out, chunked K=384
__device__ __half g_ff[ROWS*DFF];     // ff1 out, chunked K=1536
__device__ __half g_wqkv[3*EMB*EMB];  // B-chunked
__device__ __half g_wp [EMB*EMB];
__device__ __half g_w1t[DFF*EMB];
__device__ __half g_w2t[EMB*DFF];

__device__ __forceinline__ uint32_t h2u(__half2 h) {
    return *(uint32_t*)&h;
}
__device__ __forceinline__ void cp16(uint32_t saddr, const void* gptr) {
    asm volatile("cp.async.cg.shared.global [%0], [%1], 16;" :: "r"(saddr), "l"(gptr));
}
__device__ __forceinline__ uint32_t sw128(uint32_t off) {
    return off ^ ((off >> 3) & 0x70);
}
__device__ __forceinline__ void mwait(uint32_t mbar, uint32_t parity) {
    asm volatile(
        "{\n\t.reg .pred P;\n\tMW%=:\n\t"
        "mbarrier.try_wait.parity.acquire.cta.shared::cta.b64 P, [%0], %1;\n\t"
        "@!P bra MW%=;\n\t}" :: "r"(mbar), "r"(parity) : "memory");
}
__device__ __forceinline__ void bulk_ld(uint32_t saddr, const void* g, uint32_t bytes,
                                        uint32_t mbar) {
    asm volatile("cp.async.bulk.shared::cluster.global.mbarrier::complete_tx::bytes "
                 "[%0], [%1], %2, [%3];"
                 :: "r"(saddr), "l"(g), "r"(bytes), "r"(mbar) : "memory");
}

// ---- fused weight transpose + fp16 + chunked swizzle ----
__global__ void trans_all(const float* Wq, const float* Wk, const float* Wv,
                          const float* Wp, const float* W1, const float* W2,
                          __half* wqkv, __half* wp, __half* w1t, __half* w2t) {
    __shared__ float t[32][33];
    int id = blockIdx.x;
    const float* src; __half* dst; int K, N;
    if (id < 576) {
        int w = id / 144; id -= w * 144;
        src = (w == 0) ? Wq : (w == 1) ? Wk : (w == 2) ? Wv : Wp;
        dst = (w < 3) ? (wqkv + (size_t)w * EMB * EMB) : wp;
        K = 384; N = 384;
    } else if (id < 1152) { id -= 576;  src = W1; dst = w1t; K = 384;  N = 1536; }
    else                  { id -= 1152; src = W2; dst = w2t; K = 1536; N = 384;  }
    int ntn = N / 32;
    int n0 = (id % ntn) * 32, k0 = (id / ntn) * 32;
    int tx = threadIdx.x, ty = threadIdx.y;
    #pragma unroll
    for (int j = 0; j < 4; j++)
        t[ty + 8*j][tx] = src[(size_t)(k0 + ty + 8*j) * N + n0 + tx];
    __syncthreads();
    int KB = K >> 6;
    #pragma unroll
    for (int j = 0; j < 4; j++) {
        int n = n0 + ty + 8*j, k = k0 + tx;
        int blk = (n >> 7) * KB + (k >> 6);
        uint32_t bo = sw128((uint32_t)(n & 127) * 128 + (uint32_t)(k & 63) * 2);
        *(__half*)((char*)dst + (size_t)blk * 16384 + bo) = __float2half_rn(t[tx][ty + 8*j]);
    }
}

// ---- LayerNorm: warp-per-row, single-pass, float4 -> chunked fp16 (K=384) ----
__global__ void __launch_bounds__(256)
ln_kernel(const float* __restrict__ x, const float* __restrict__ g,
          const float* __restrict__ b, __half* __restrict__ out) {
    int warp = threadIdx.x >> 5, lane = threadIdx.x & 31;
    int row = blockIdx.x * 8 + warp;
    const float4* xr = (const float4*)(x + (size_t)row * EMB);
    float4 v[3];
    float s1 = 0.f, s2 = 0.f;
    #pragma unroll
    for (int j = 0; j < 3; j++) {
        v[j] = xr[lane + 32 * j];
        s1 += v[j].x + v[j].y + v[j].z + v[j].w;
        s2 += v[j].x*v[j].x + v[j].y*v[j].y + v[j].z*v[j].z + v[j].w*v[j].w;
    }
    #pragma unroll
    for (int o = 16; o; o >>= 1) {
        s1 += __shfl_xor_sync(0xffffffffu, s1, o);
        s2 += __shfl_xor_sync(0xffffffffu, s2, o);
    }
    float mu = s1 * (1.0f / EMB);
    float var = s2 * (1.0f / EMB) - mu * mu;
    float inv = rsqrtf(var + 1e-5f);

    char* ob = (char*)out;
    uint32_t rb = (uint32_t)(row & 127) * 128;
    int mb6 = (row >> 7) * 6;
    #pragma unroll
    for (int j = 0; j < 3; j++) {
        int k = (lane + 32 * j) * 4;
        float4 gv = *(const float4*)&g[k];
        float4 bv = *(const float4*)&b[k];
        float o0 = (v[j].x - mu) * inv * gv.x + bv.x;
        float o1 = (v[j].y - mu) * inv * gv.y + bv.y;
        float o2 = (v[j].z - mu) * inv * gv.z + bv.z;
        float o3 = (v[j].w - mu) * inv * gv.w + bv.w;
        uint2 u;
        u.x = h2u(__floats2half2_rn(o0, o1));
        u.y = h2u(__floats2half2_rn(o2, o3));
        *(uint2*)(ob + (size_t)(mb6 + (k >> 6)) * 16384 + sw128(rb + (uint32_t)(k & 63) * 2)) = u;
    }
}

// ---- FP16 warp-MMA GEMM with bulk-copy loads (R11, unchanged) ----
#define HG_HDR 1024
#define HG_BUF 16384
#define HG_STAGE (2 * HG_BUF)
#define HG_SMEM (HG_HDR + 3 * HG_STAGE)

template<int EPI>
__global__ void __launch_bounds__(256)
hgemm(const __half* __restrict__ A, const __half* __restrict__ W,
      const float* __restrict__ bias, const float* __restrict__ R,
      void* __restrict__ Cv, __half* qO, __half* kO, __half* vO, int N, int K) {
    extern __shared__ char smem[];
    uint32_t sb = (uint32_t)__cvta_generic_to_shared(smem);
    int tid  = threadIdx.x;
    int lane = tid & 31, warp = tid >> 5;
    int wm = warp >> 2, wn = warp & 3;
    int l4 = lane >> 2, qq = lane & 3;
    int n0 = blockIdx.x * 128, m0 = blockIdx.y * 128;
    int KB = K >> 6;
    int mbA = blockIdx.y, nbB = blockIdx.x;
    const char* Ab = (const char*)A;
    const char* Wb = (const char*)W;

    if (tid < 3)
        asm volatile("mbarrier.init.shared.b64 [%0], 1;" :: "r"(sb + tid * 8) : "memory");
    __syncthreads();

    auto load = [&](int c) {
        int st = c % 3;
        uint32_t mb = sb + st * 8;
        uint32_t d  = sb + HG_HDR + (uint32_t)st * HG_STAGE;
        asm volatile("mbarrier.arrive.expect_tx.shared.b64 _, [%0], %1;"
                     :: "r"(mb), "r"((uint32_t)HG_STAGE) : "memory");
        bulk_ld(d,          Ab + (size_t)(mbA * KB + c) * HG_BUF, HG_BUF, mb);
        bulk_ld(d + HG_BUF, Wb + (size_t)(nbB * KB + c) * HG_BUF, HG_BUF, mb);
    };
    if (tid == 0) { load(0); load(1); }

    float acc[4][4][4];
    #pragma unroll
    for (int mt = 0; mt < 4; mt++)
        #pragma unroll
        for (int nt = 0; nt < 4; nt++)
            #pragma unroll
            for (int e = 0; e < 4; e++) acc[mt][nt][e] = 0.f;

    for (int c = 0; c < KB; c++) {
        int st = c % 3;
        mwait(sb + st * 8, (uint32_t)((c / 3) & 1));
        const char* As = smem + HG_HDR + (size_t)st * HG_STAGE;
        const char* Bs = As + HG_BUF;

        #pragma unroll
        for (int kk = 0; kk < 4; kk++) {
            int kb = kk * 8;
            uint32_t af[4][4], bf[4][2];
            #pragma unroll
            for (int mt = 0; mt < 4; mt++) {
                int mr = wm * 64 + mt * 16 + l4;
                af[mt][0] = *(const uint32_t*)(As + sw128((uint32_t)mr * 128 + (kb + qq) * 4));
                af[mt][1] = *(const uint32_t*)(As + sw128((uint32_t)(mr + 8) * 128 + (kb + qq) * 4));
                af[mt][2] = *(const uint32_t*)(As + sw128((uint32_t)mr * 128 + (kb + qq + 4) * 4));
                af[mt][3] = *(const uint32_t*)(As + sw128((uint32_t)(mr + 8) * 128 + (kb + qq + 4) * 4));
            }
            #pragma unroll
            for (int nt = 0; nt < 4; nt++) {
                int nr = wn * 32 + nt * 8 + l4;
                bf[nt][0] = *(const uint32_t*)(Bs + sw128((uint32_t)nr * 128 + (kb + qq) * 4));
                bf[nt][1] = *(const uint32_t*)(Bs + sw128((uint32_t)nr * 128 + (kb + qq + 4) * 4));
            }
            #pragma unroll
            for (int mt = 0; mt < 4; mt++)
                #pragma unroll
                for (int nt = 0; nt < 4; nt++)
                    asm volatile(
                        "mma.sync.aligned.m16n8k16.row.col.f32.f16.f16.f32 "
                        "{%0,%1,%2,%3}, {%4,%5,%6,%7}, {%8,%9}, {%0,%1,%2,%3};"
                        : "+f"(acc[mt][nt][0]), "+f"(acc[mt][nt][1]),
                          "+f"(acc[mt][nt][2]), "+f"(acc[mt][nt][3])
                        : "r"(af[mt][0]), "r"(af[mt][1]), "r"(af[mt][2]), "r"(af[mt][3]),
                          "r"(bf[nt][0]), "r"(bf[nt][1]));
        }
        __syncthreads();
        if (c + 2 < KB && tid == 0) load(c + 2);
    }

    #pragma unroll
    for (int mt = 0; mt < 4; mt++) {
        #pragma unroll
        for (int nt = 0; nt < 4; nt++) {
            int nb = n0 + wn * 32 + nt * 8 + qq * 2;
            int mA = m0 + wm * 64 + mt * 16 + l4;
            float v0 = acc[mt][nt][0], v1 = acc[mt][nt][1];
            float v2 = acc[mt][nt][2], v3 = acc[mt][nt][3];
            if (EPI == 0) {
                int mat = nb / 384, nn = nb - mat * 384;
                int head = nn >> 6, d = nn & 63;
                int b_ = mA >> 9, tA = mA & 511;
                if (mat == 0) { v0 *= 0.125f; v1 *= 0.125f; v2 *= 0.125f; v3 *= 0.125f; }
                if (mat < 2) {
                    __half* base = mat ? kO : qO;
                    size_t off0 = ((size_t)(b_ * HEADS + head) * TT + tA) * 64 + d;
                    *(__half2*)&base[off0]          = __floats2half2_rn(v0, v1);
                    *(__half2*)&base[off0 + 8 * 64] = __floats2half2_rn(v2, v3);
                } else {
                    size_t off0 = ((size_t)(b_ * HEADS + head) * 64 + d) * TT + tA;
                    vO[off0]          = __float2half_rn(v0);
                    vO[off0 + TT]     = __float2half_rn(v1);
                    vO[off0 + 8]      = __float2half_rn(v2);
                    vO[off0 + TT + 8] = __float2half_rn(v3);
                }
            } else if (EPI == 1) {
                float* Cf = (float*)Cv;
                size_t o0 = (size_t)mA * N + nb;
                size_t o1 = (size_t)(mA + 8) * N + nb;
                Cf[o0]     = v0 + bias[nb]     + R[o0];
                Cf[o0 + 1] = v1 + bias[nb + 1] + R[o0 + 1];
                Cf[o1]     = v2 + bias[nb]     + R[o1];
                Cf[o1 + 1] = v3 + bias[nb + 1] + R[o1 + 1];
            } else {
                char* Ch = (char*)Cv;
                v0 += bias[nb];     v1 += bias[nb + 1];
                v2 += bias[nb];     v3 += bias[nb + 1];
                v0 = v0 > 0.f ? v0 : 0.f;  v1 = v1 > 0.f ? v1 : 0.f;
                v2 = v2 > 0.f ? v2 : 0.f;  v3 = v3 > 0.f ? v3 : 0.f;
                int blk = (mA >> 7) * (N >> 6) + (nb >> 6);
                uint32_t b0 = sw128((uint32_t)(mA & 127) * 128 + (uint32_t)(nb & 63) * 2);
                uint32_t b1 = sw128((uint32_t)((mA + 8) & 127) * 128 + (uint32_t)(nb & 63) * 2);
                *(__half2*)(Ch + (size_t)blk * 16384 + b0) = __floats2half2_rn(v0, v1);
                *(__half2*)(Ch + (size_t)blk * 16384 + b1) = __floats2half2_rn(v2, v3);
            }
        }
    }
}

// ---- fp16 flash attention: register-direct P (no smem round-trip) ----
#define ASTR 36
#define KVW (64 * ASTR)
#define AT_K0 0
#define AT_K1 KVW
#define AT_V0 (2 * KVW)
#define AT_V1 (3 * KVW)
#define ATTN_SMEM (4 * KVW * 4)    // 36864

__global__ void __launch_bounds__(256)
attn3_kernel(const __half* __restrict__ q, const __half* __restrict__ k,
             const __half* __restrict__ v, __half* __restrict__ o) {
    extern __shared__ uint32_t sm2[];
    uint32_t sbase = (uint32_t)__cvta_generic_to_shared(sm2);
    int tid = threadIdx.x, lane = tid & 31, warp = tid >> 5;
    int l4 = lane >> 2, qq = lane & 3;
    int bh = blockIdx.y, q0 = blockIdx.x * 128;
    int mrow = warp * 16 + l4, qg0 = q0 + mrow, qg1 = qg0 + 8;
    int ktiles = (q0 + 128) >> 6;
    int lr = tid >> 2, lc = tid & 3;
    const __half* kh = k + (size_t)bh * TT * 64;
    const __half* vh = v + (size_t)bh * 64 * TT;

    #pragma unroll
    for (int it = 0; it < 2; it++) {
        int c = lc + it * 4;
        cp16(sbase + (AT_K0 + lr * ASTR + c * 4) * 4, kh + (size_t)lr * 64 + c * 8);
        cp16(sbase + (AT_V0 + lr * ASTR + c * 4) * 4, vh + (size_t)lr * TT + c * 8);
    }
    asm volatile("cp.async.commit_group;");

    const uint32_t* qw = (const uint32_t*)(q + (size_t)bh * TT * 64);
    uint32_t qf[4][4];
    #pragma unroll
    for (int kk = 0; kk < 4; kk++) {
        int kb = kk * 8;
        qf[kk][0] = qw[qg0 * 32 + kb + qq];
        qf[kk][1] = qw[qg1 * 32 + kb + qq];
        qf[kk][2] = qw[qg0 * 32 + kb + qq + 4];
        qf[kk][3] = qw[qg1 * 32 + kb + qq + 4];
    }

    float Oa[8][4];
    #pragma unroll
    for (int nt = 0; nt < 8; nt++)
        #pragma unroll
        for (int e = 0; e < 4; e++) Oa[nt][e] = 0.f;
    float m0 = -1e30f, m1 = -1e30f, l0 = 0.f, l1 = 0.f;

    for (int kt = 0; kt < ktiles; kt++) {
        asm volatile("cp.async.wait_group 0;");
        __syncthreads();
        if (kt + 1 < ktiles) {
            int nb = (kt + 1) & 1, k0n = (kt + 1) << 6;
            uint32_t kd = (nb ? AT_K1 : AT_K0), vd = (nb ? AT_V1 : AT_V0);
            #pragma unroll
            for (int it = 0; it < 2; it++) {
                int c = lc + it * 4;
                cp16(sbase + (kd + lr * ASTR + c * 4) * 4, kh + (size_t)(k0n + lr) * 64 + c * 8);
                cp16(sbase + (vd + lr * ASTR + c * 4) * 4, vh + (size_t)lr * TT + k0n + c * 8);
            }
            asm volatile("cp.async.commit_group;");
        }
        uint32_t* Ks = sm2 + ((kt & 1) ? AT_K1 : AT_K0);
        uint32_t* Vs = sm2 + ((kt & 1) ? AT_V1 : AT_V0);
        int k0 = kt << 6;

        float s[8][4];
        #pragma unroll
        for (int nt = 0; nt < 8; nt++)
            #pragma unroll
            for (int e = 0; e < 4; e++) s[nt][e] = 0.f;
        #pragma unroll
        for (int kk = 0; kk < 4; kk++) {
            int kb = kk * 8;
            #pragma unroll
            for (int nt = 0; nt < 8; nt++) {
                uint32_t b0 = Ks[(nt * 8 + l4) * ASTR + kb + qq];
                uint32_t b1 = Ks[(nt * 8 + l4) * ASTR + kb + qq + 4];
                asm volatile(
                    "mma.sync.aligned.m16n8k16.row.col.f32.f16.f16.f32 "
                    "{%0,%1,%2,%3}, {%4,%5,%6,%7}, {%8,%9}, {%0,%1,%2,%3};"
                    : "+f"(s[nt][0]), "+f"(s[nt][1]), "+f"(s[nt][2]), "+f"(s[nt][3])
                    : "r"(qf[kk][0]), "r"(qf[kk][1]), "r"(qf[kk][2]), "r"(qf[kk][3]),
                      "r"(b0), "r"(b1));
            }
        }
        if (k0 + 63 > qg0) {
            #pragma unroll
            for (int nt = 0; nt < 8; nt++) {
                int kg = k0 + nt * 8 + 2 * qq;
                if (kg     > qg0) s[nt][0] = -1e30f;
                if (kg + 1 > qg0) s[nt][1] = -1e30f;
                if (kg     > qg1) s[nt][2] = -1e30f;
                if (kg + 1 > qg1) s[nt][3] = -1e30f;
            }
        }
        float r0 = -1e30f, r1 = -1e30f;
        #pragma unroll
        for (int nt = 0; nt < 8; nt++) {
            r0 = fmaxf(r0, fmaxf(s[nt][0], s[nt][1]));
            r1 = fmaxf(r1, fmaxf(s[nt][2], s[nt][3]));
        }
        r0 = fmaxf(r0, __shfl_xor_sync(0xffffffffu, r0, 1));
        r0 = fmaxf(r0, __shfl_xor_sync(0xffffffffu, r0, 2));
        r1 = fmaxf(r1, __shfl_xor_sync(0xffffffffu, r1, 1));
        r1 = fmaxf(r1, __shfl_xor_sync(0xffffffffu, r1, 2));
        float mn0 = fmaxf(m0, r0), mn1 = fmaxf(m1, r1);
        float sc0 = __expf(m0 - mn0), sc1 = __expf(m1 - mn1);
        float rs0 = 0.f, rs1 = 0.f;
        #pragma unroll
        for (int nt = 0; nt < 8; nt++) {
            s[nt][0] = __expf(s[nt][0] - mn0);
            s[nt][1] = __expf(s[nt][1] - mn0);
            s[nt][2] = __expf(s[nt][2] - mn1);
            s[nt][3] = __expf(s[nt][3] - mn1);
            rs0 += s[nt][0] + s[nt][1];
            rs1 += s[nt][2] + s[nt][3];
        }
        rs0 += __shfl_xor_sync(0xffffffffu, rs0, 1);
        rs0 += __shfl_xor_sync(0xffffffffu, rs0, 2);
        rs1 += __shfl_xor_sync(0xffffffffu, rs1, 1);
        rs1 += __shfl_xor_sync(0xffffffffu, rs1, 2);
        l0 = l0 * sc0 + rs0;  l1 = l1 * sc1 + rs1;
        m0 = mn0;  m1 = mn1;
        #pragma unroll
        for (int nt = 0; nt < 8; nt++) {
            Oa[nt][0] *= sc0; Oa[nt][1] *= sc0;
            Oa[nt][2] *= sc1; Oa[nt][3] *= sc1;
        }

        // ---- PV: A-fragments straight from s registers ----
        // C-frag ownership (rows l4/l4+8, cols 2qq/2qq+1 of each n8 tile) matches
        // A-frag ownership for k16 chunk kk: keys 16kk+2qq(+1) = s[2kk],
        // keys 16kk+8+2qq(+1) = s[2kk+1].
        #pragma unroll
        for (int kk = 0; kk < 4; kk++) {
            uint32_t af[4];
            af[0] = h2u(__floats2half2_rn(s[2*kk][0],   s[2*kk][1]));
            af[1] = h2u(__floats2half2_rn(s[2*kk][2],   s[2*kk][3]));
            af[2] = h2u(__floats2half2_rn(s[2*kk+1][0], s[2*kk+1][1]));
            af[3] = h2u(__floats2half2_rn(s[2*kk+1][2], s[2*kk+1][3]));
            int kb = kk * 8;
            #pragma unroll
            for (int nt = 0; nt < 8; nt++) {
                uint32_t b0 = Vs[(nt * 8 + l4) * ASTR + kb + qq];
                uint32_t b1 = Vs[(nt * 8 + l4) * ASTR + kb + qq + 4];
                asm volatile(
                    "mma.sync.aligned.m16n8k16.row.col.f32.f16.f16.f32 "
                    "{%0,%1,%2,%3}, {%4,%5,%6,%7}, {%8,%9}, {%0,%1,%2,%3};"
                    : "+f"(Oa[nt][0]), "+f"(Oa[nt][1]), "+f"(Oa[nt][2]), "+f"(Oa[nt][3])
                    : "r"(af[0]), "r"(af[1]), "r"(af[2]), "r"(af[3]), "r"(b0), "r"(b1));
            }
        }
    }

    int b_ = bh / HEADS, h_ = bh % HEADS;
    float inv0 = 1.f / l0, inv1 = 1.f / l1;
    char* ob = (char*)o;
    int row0 = b_ * TT + qg0, row1 = b_ * TT + qg1;
    size_t blk0 = (size_t)((row0 >> 7) * 6 + h_) * 16384;
    size_t blk1 = (size_t)((row1 >> 7) * 6 + h_) * 16384;
    uint32_t rb0 = (uint32_t)(row0 & 127) * 128, rb1 = (uint32_t)(row1 & 127) * 128;
    #pragma unroll
    for (int nt = 0; nt < 8; nt++) {
        uint32_t co = (uint32_t)(nt * 8 + 2 * qq) * 2;
        *(__half2*)(ob + blk0 + sw128(rb0 + co)) = __floats2half2_rn(Oa[nt][0] * inv0, Oa[nt][1] * inv0);
        *(__half2*)(ob + blk1 + sw128(rb1 + co)) = __floats2half2_rn(Oa[nt][2] * inv1, Oa[nt][3] * inv1);
    }
}

// ---------------- launch ----------------
extern "C" void kernel_launch(void* const* d_in, const int* in_sizes, int n_in,
                              void* d_out, int out_size) {
    const float* x   = (const float*)d_in[0];
    const float* Wq  = (const float*)d_in[1];
    const float* Wk  = (const float*)d_in[2];
    const float* Wv  = (const float*)d_in[3];
    const float* Wp  = (const float*)d_in[4];
    const float* bp  = (const float*)d_in[5];
    const float* g1  = (const float*)d_in[6];
    const float* b1  = (const float*)d_in[7];
    const float* g2  = (const float*)d_in[8];
    const float* b2  = (const float*)d_in[9];
    const float* W1  = (const float*)d_in[10];
    const float* bf1 = (const float*)d_in[11];
    const float* W2  = (const float*)d_in[12];
    const float* bf2 = (const float*)d_in[13];
    float* out = (float*)d_out;

    __half *h, *q, *k, *v, *o, *h2, *ff, *wqkv, *wp, *w1t, *w2t;
    cudaGetSymbolAddress((void**)&h,    g_h);
    cudaGetSymbolAddress((void**)&q,    g_q);
    cudaGetSymbolAddress((void**)&k,    g_k);
    cudaGetSymbolAddress((void**)&v,    g_v);
    cudaGetSymbolAddress((void**)&o,    g_o);
    cudaGetSymbolAddress((void**)&h2,   g_h2);
    cudaGetSymbolAddress((void**)&ff,   g_ff);
    cudaGetSymbolAddress((void**)&wqkv, g_wqkv);
    cudaGetSymbolAddress((void**)&wp,   g_wp);
    cudaGetSymbolAddress((void**)&w1t,  g_w1t);
    cudaGetSymbolAddress((void**)&w2t,  g_w2t);

    static bool attr_done = false;
    if (!attr_done) {
        cudaFuncSetAttribute(attn3_kernel, cudaFuncAttributeMaxDynamicSharedMemorySize, (int)ATTN_SMEM);
        cudaFuncSetAttribute(hgemm<0>, cudaFuncAttributeMaxDynamicSharedMemorySize, (int)HG_SMEM);
        cudaFuncSetAttribute(hgemm<1>, cudaFuncAttributeMaxDynamicSharedMemorySize, (int)HG_SMEM);
        cudaFuncSetAttribute(hgemm<2>, cudaFuncAttributeMaxDynamicSharedMemorySize, (int)HG_SMEM);
        attr_done = true;
    }

    trans_all<<<1728, dim3(32, 8)>>>(Wq, Wk, Wv, Wp, W1, W2, wqkv, wp, w1t, w2t);
    ln_kernel<<<ROWS / 8, 256>>>(x, g1, b1, h);
    hgemm<0><<<dim3(9, ROWS/128), 256, HG_SMEM>>>(h, wqkv, nullptr, nullptr, nullptr, q, k, v, 1152, 384);
    attn3_kernel<<<dim3(TT/128, BB*HEADS), 256, ATTN_SMEM>>>(q, k, v, o);
    hgemm<1><<<dim3(3, ROWS/128), 256, HG_SMEM>>>(o, wp, bp, x, out, nullptr, nullptr, nullptr, 384, 384);
    ln_kernel<<<ROWS / 8, 256>>>(out, g2, b2, h2);
    hgemm<2><<<dim3(12, ROWS/128), 256, HG_SMEM>>>(h2, w1t, bf1, nullptr, ff, nullptr, nullptr, nullptr, 1536, 384);
    hgemm<1><<<dim3(3, ROWS/128), 256, HG_SMEM>>>(ff, w2t, bf2, out, out, nullptr, nullptr, nullptr, 384, 1536);
}

// round 14
// speedup vs baseline: 2.7179x; 1.1290x over previous
#include <cuda_runtime.h>
#include <cuda_fp16.h>
#include <stdint.h>

#define EMB   384
#define HEADS 6
#define DFF   1536
#define BB    32
#define TT    512
#define ROWS  (BB*TT)

// Chunked-SW128 layout: 16KB blocks of [128 rows][64 halves];
// block = (row>>7)*(K/64) + (k>>6); byte = sw128((row&127)*128 + (k&63)*2)
__device__ __half g_h [ROWS*EMB];
__device__ __half g_q [ROWS*EMB];     // [B,H,T,D] linear, pre-scaled 1/8
__device__ __half g_k [ROWS*EMB];     // [B,H,T,D] linear
__device__ __half g_v [ROWS*EMB];     // [B,H,D,T] linear (transposed)
__device__ __half g_o [ROWS*EMB];     // attn out, chunked K=384
__device__ __half g_h2[ROWS*EMB];
__device__ __half g_ff[ROWS*DFF];
__device__ __half g_wqkv[3*EMB*EMB];
__device__ __half g_wp [EMB*EMB];
__device__ __half g_w1t[DFF*EMB];
__device__ __half g_w2t[EMB*DFF];

__device__ __forceinline__ uint32_t h2u(__half2 h) { return *(uint32_t*)&h; }
__device__ __forceinline__ void cp16(uint32_t saddr, const void* gptr) {
    asm volatile("cp.async.cg.shared.global [%0], [%1], 16;" :: "r"(saddr), "l"(gptr));
}
__device__ __forceinline__ uint32_t sw128(uint32_t off) {
    return off ^ ((off >> 3) & 0x70);
}
__device__ __forceinline__ void mwait(uint32_t mbar, uint32_t parity) {
    asm volatile(
        "{\n\t.reg .pred P;\n\tMW%=:\n\t"
        "mbarrier.try_wait.parity.acquire.cta.shared::cta.b64 P, [%0], %1;\n\t"
        "@!P bra MW%=;\n\t}" :: "r"(mbar), "r"(parity) : "memory");
}
__device__ __forceinline__ void bulk_ld(uint32_t saddr, const void* g, uint32_t bytes,
                                        uint32_t mbar) {
    asm volatile("cp.async.bulk.shared::cluster.global.mbarrier::complete_tx::bytes "
                 "[%0], [%1], %2, [%3];"
                 :: "r"(saddr), "l"(g), "r"(bytes), "r"(mbar) : "memory");
}
__device__ __forceinline__ void ldsm4(uint32_t& r0, uint32_t& r1, uint32_t& r2,
                                      uint32_t& r3, uint32_t a) {
    asm volatile("ldmatrix.sync.aligned.m8n8.x4.shared.b16 {%0,%1,%2,%3}, [%4];"
                 : "=r"(r0), "=r"(r1), "=r"(r2), "=r"(r3) : "r"(a));
}

// ---- fused weight transpose + fp16 + chunked swizzle ----
__global__ void trans_all(const float* Wq, const float* Wk, const float* Wv,
                          const float* Wp, const float* W1, const float* W2,
                          __half* wqkv, __half* wp, __half* w1t, __half* w2t) {
    __shared__ float t[32][33];
    int id = blockIdx.x;
    const float* src; __half* dst; int K, N;
    if (id < 576) {
        int w = id / 144; id -= w * 144;
        src = (w == 0) ? Wq : (w == 1) ? Wk : (w == 2) ? Wv : Wp;
        dst = (w < 3) ? (wqkv + (size_t)w * EMB * EMB) : wp;
        K = 384; N = 384;
    } else if (id < 1152) { id -= 576;  src = W1; dst = w1t; K = 384;  N = 1536; }
    else                  { id -= 1152; src = W2; dst = w2t; K = 1536; N = 384;  }
    int ntn = N / 32;
    int n0 = (id % ntn) * 32, k0 = (id / ntn) * 32;
    int tx = threadIdx.x, ty = threadIdx.y;
    #pragma unroll
    for (int j = 0; j < 4; j++)
        t[ty + 8*j][tx] = src[(size_t)(k0 + ty + 8*j) * N + n0 + tx];
    __syncthreads();
    int KB = K >> 6;
    #pragma unroll
    for (int j = 0; j < 4; j++) {
        int n = n0 + ty + 8*j, k = k0 + tx;
        int blk = (n >> 7) * KB + (k >> 6);
        uint32_t bo = sw128((uint32_t)(n & 127) * 128 + (uint32_t)(k & 63) * 2);
        *(__half*)((char*)dst + (size_t)blk * 16384 + bo) = __float2half_rn(t[tx][ty + 8*j]);
    }
}

// ---- LayerNorm: warp-per-row, single-pass, float4 -> chunked fp16 (K=384) ----
__global__ void __launch_bounds__(256)
ln_kernel(const float* __restrict__ x, const float* __restrict__ g,
          const float* __restrict__ b, __half* __restrict__ out) {
    int warp = threadIdx.x >> 5, lane = threadIdx.x & 31;
    int row = blockIdx.x * 8 + warp;
    const float4* xr = (const float4*)(x + (size_t)row * EMB);
    float4 v[3];
    float s1 = 0.f, s2 = 0.f;
    #pragma unroll
    for (int j = 0; j < 3; j++) {
        v[j] = xr[lane + 32 * j];
        s1 += v[j].x + v[j].y + v[j].z + v[j].w;
        s2 += v[j].x*v[j].x + v[j].y*v[j].y + v[j].z*v[j].z + v[j].w*v[j].w;
    }
    #pragma unroll
    for (int o = 16; o; o >>= 1) {
        s1 += __shfl_xor_sync(0xffffffffu, s1, o);
        s2 += __shfl_xor_sync(0xffffffffu, s2, o);
    }
    float mu = s1 * (1.0f / EMB);
    float var = s2 * (1.0f / EMB) - mu * mu;
    float inv = rsqrtf(var + 1e-5f);

    char* ob = (char*)out;
    uint32_t rb = (uint32_t)(row & 127) * 128;
    int mb6 = (row >> 7) * 6;
    #pragma unroll
    for (int j = 0; j < 3; j++) {
        int k = (lane + 32 * j) * 4;
        float4 gv = *(const float4*)&g[k];
        float4 bv = *(const float4*)&b[k];
        float o0 = (v[j].x - mu) * inv * gv.x + bv.x;
        float o1 = (v[j].y - mu) * inv * gv.y + bv.y;
        float o2 = (v[j].z - mu) * inv * gv.z + bv.z;
        float o3 = (v[j].w - mu) * inv * gv.w + bv.w;
        uint2 u;
        u.x = h2u(__floats2half2_rn(o0, o1));
        u.y = h2u(__floats2half2_rn(o2, o3));
        *(uint2*)(ob + (size_t)(mb6 + (k >> 6)) * 16384 + sw128(rb + (uint32_t)(k & 63) * 2)) = u;
    }
}

// ---- FP16 warp-MMA GEMM: bulk-copy loads + ldmatrix fragments ----
#define HG_HDR 1024
#define HG_BUF 16384
#define HG_STAGE (2 * HG_BUF)
#define HG_SMEM (HG_HDR + 3 * HG_STAGE)

template<int EPI>
__global__ void __launch_bounds__(256)
hgemm(const __half* __restrict__ A, const __half* __restrict__ W,
      const float* __restrict__ bias, const float* __restrict__ R,
      void* __restrict__ Cv, __half* qO, __half* kO, __half* vO, int N, int K) {
    extern __shared__ char smem[];
    uint32_t sb = (uint32_t)__cvta_generic_to_shared(smem);
    int tid  = threadIdx.x;
    int lane = tid & 31, warp = tid >> 5;
    int wm = warp >> 2, wn = warp & 3;
    int l4 = lane >> 2, qq = lane & 3;
    int n0 = blockIdx.x * 128, m0 = blockIdx.y * 128;
    int KB = K >> 6;
    int mbA = blockIdx.y, nbB = blockIdx.x;
    const char* Ab = (const char*)A;
    const char* Wb = (const char*)W;

    // ldmatrix per-lane address components
    uint32_t aRow = (uint32_t)((lane & 7) + ((lane >> 3) & 1) * 8);
    uint32_t aSel = (uint32_t)((lane >> 4) * 16);
    uint32_t bRow = (uint32_t)(((lane >> 4) & 1) * 8 + (lane & 7));
    uint32_t bSel = (uint32_t)(((lane >> 3) & 1) * 16);
    uint32_t xm   = (uint32_t)((lane & 7) << 4);
    uint32_t aBase = (uint32_t)(wm * 64) + aRow;      // + mt*16
    uint32_t bBase = (uint32_t)(wn * 32) + bRow;      // + pair*16

    if (tid < 3)
        asm volatile("mbarrier.init.shared.b64 [%0], 1;" :: "r"(sb + tid * 8) : "memory");
    __syncthreads();

    auto load = [&](int c) {
        int st = c % 3;
        uint32_t mb = sb + st * 8;
        uint32_t d  = sb + HG_HDR + (uint32_t)st * HG_STAGE;
        asm volatile("mbarrier.arrive.expect_tx.shared.b64 _, [%0], %1;"
                     :: "r"(mb), "r"((uint32_t)HG_STAGE) : "memory");
        bulk_ld(d,          Ab + (size_t)(mbA * KB + c) * HG_BUF, HG_BUF, mb);
        bulk_ld(d + HG_BUF, Wb + (size_t)(nbB * KB + c) * HG_BUF, HG_BUF, mb);
    };
    if (tid == 0) { load(0); load(1); }

    float acc[4][4][4];
    #pragma unroll
    for (int mt = 0; mt < 4; mt++)
        #pragma unroll
        for (int nt = 0; nt < 4; nt++)
            #pragma unroll
            for (int e = 0; e < 4; e++) acc[mt][nt][e] = 0.f;

    for (int c = 0; c < KB; c++) {
        int st = c % 3;
        mwait(sb + st * 8, (uint32_t)((c / 3) & 1));
        uint32_t As = sb + HG_HDR + (uint32_t)st * HG_STAGE;
        uint32_t Bs = As + HG_BUF;

        #pragma unroll
        for (int kk = 0; kk < 4; kk++) {
            uint32_t af[4][4], bf[4][2];
            #pragma unroll
            for (int mt = 0; mt < 4; mt++)
                ldsm4(af[mt][0], af[mt][1], af[mt][2], af[mt][3],
                      As + (aBase + mt * 16) * 128 + ((32u * kk + aSel) ^ xm));
            #pragma unroll
            for (int pr = 0; pr < 2; pr++)
                ldsm4(bf[2*pr][0], bf[2*pr][1], bf[2*pr+1][0], bf[2*pr+1][1],
                      Bs + (bBase + pr * 16) * 128 + ((32u * kk + bSel) ^ xm));
            #pragma unroll
            for (int mt = 0; mt < 4; mt++)
                #pragma unroll
                for (int nt = 0; nt < 4; nt++)
                    asm volatile(
                        "mma.sync.aligned.m16n8k16.row.col.f32.f16.f16.f32 "
                        "{%0,%1,%2,%3}, {%4,%5,%6,%7}, {%8,%9}, {%0,%1,%2,%3};"
                        : "+f"(acc[mt][nt][0]), "+f"(acc[mt][nt][1]),
                          "+f"(acc[mt][nt][2]), "+f"(acc[mt][nt][3])
                        : "r"(af[mt][0]), "r"(af[mt][1]), "r"(af[mt][2]), "r"(af[mt][3]),
                          "r"(bf[nt][0]), "r"(bf[nt][1]));
        }
        __syncthreads();
        if (c + 2 < KB && tid == 0) load(c + 2);
    }

    #pragma unroll
    for (int mt = 0; mt < 4; mt++) {
        #pragma unroll
        for (int nt = 0; nt < 4; nt++) {
            int nb = n0 + wn * 32 + nt * 8 + qq * 2;
            int mA = m0 + wm * 64 + mt * 16 + l4;
            float v0 = acc[mt][nt][0], v1 = acc[mt][nt][1];
            float v2 = acc[mt][nt][2], v3 = acc[mt][nt][3];
            if (EPI == 0) {
                int mat = nb / 384, nn = nb - mat * 384;
                int head = nn >> 6, d = nn & 63;
                int b_ = mA >> 9, tA = mA & 511;
                if (mat == 0) { v0 *= 0.125f; v1 *= 0.125f; v2 *= 0.125f; v3 *= 0.125f; }
                if (mat < 2) {
                    __half* base = mat ? kO : qO;
                    size_t off0 = ((size_t)(b_ * HEADS + head) * TT + tA) * 64 + d;
                    *(__half2*)&base[off0]          = __floats2half2_rn(v0, v1);
                    *(__half2*)&base[off0 + 8 * 64] = __floats2half2_rn(v2, v3);
                } else {
                    size_t off0 = ((size_t)(b_ * HEADS + head) * 64 + d) * TT + tA;
                    vO[off0]          = __float2half_rn(v0);
                    vO[off0 + TT]     = __float2half_rn(v1);
                    vO[off0 + 8]      = __float2half_rn(v2);
                    vO[off0 + TT + 8] = __float2half_rn(v3);
                }
            } else if (EPI == 1) {
                float* Cf = (float*)Cv;
                size_t o0 = (size_t)mA * N + nb;
                size_t o1 = (size_t)(mA + 8) * N + nb;
                Cf[o0]     = v0 + bias[nb]     + R[o0];
                Cf[o0 + 1] = v1 + bias[nb + 1] + R[o0 + 1];
                Cf[o1]     = v2 + bias[nb]     + R[o1];
                Cf[o1 + 1] = v3 + bias[nb + 1] + R[o1 + 1];
            } else {
                char* Ch = (char*)Cv;
                v0 += bias[nb];     v1 += bias[nb + 1];
                v2 += bias[nb];     v3 += bias[nb + 1];
                v0 = v0 > 0.f ? v0 : 0.f;  v1 = v1 > 0.f ? v1 : 0.f;
                v2 = v2 > 0.f ? v2 : 0.f;  v3 = v3 > 0.f ? v3 : 0.f;
                int blk = (mA >> 7) * (N >> 6) + (nb >> 6);
                uint32_t b0 = sw128((uint32_t)(mA & 127) * 128 + (uint32_t)(nb & 63) * 2);
                uint32_t b1 = sw128((uint32_t)((mA + 8) & 127) * 128 + (uint32_t)(nb & 63) * 2);
                *(__half2*)(Ch + (size_t)blk * 16384 + b0) = __floats2half2_rn(v0, v1);
                *(__half2*)(Ch + (size_t)blk * 16384 + b1) = __floats2half2_rn(v2, v3);
            }
        }
    }
}

// ---- fp16 flash attention: ldmatrix K/V + register-direct P ----
// K/V smem tiles: 64 rows x 128B, SW128-swizzled rows.
#define KVB 8192
#define AT_K0 0
#define AT_K1 KVB
#define AT_V0 (2 * KVB)
#define AT_V1 (3 * KVB)
#define ATTN_SMEM (4 * KVB)   // 32768

__global__ void __launch_bounds__(256)
attn3_kernel(const __half* __restrict__ q, const __half* __restrict__ k,
             const __half* __restrict__ v, __half* __restrict__ o) {
    extern __shared__ char sm2[];
    uint32_t sbase = (uint32_t)__cvta_generic_to_shared(sm2);
    int tid = threadIdx.x, lane = tid & 31, warp = tid >> 5;
    int l4 = lane >> 2, qq = lane & 3;
    int bh = blockIdx.y, q0 = blockIdx.x * 128;
    int mrow = warp * 16 + l4, qg0 = q0 + mrow, qg1 = qg0 + 8;
    int ktiles = (q0 + 128) >> 6;
    int lr = tid >> 2, lc = tid & 3;
    uint32_t lxm = (uint32_t)((lr & 7) << 4);
    const __half* kh = k + (size_t)bh * TT * 64;
    const __half* vh = v + (size_t)bh * 64 * TT;

    // ldmatrix B-pattern lane addressing (rows = n-or-key index)
    uint32_t bRow = (uint32_t)(((lane >> 4) & 1) * 8 + (lane & 7));
    uint32_t bSel = (uint32_t)(((lane >> 3) & 1) * 16);
    uint32_t xm   = (uint32_t)((lane & 7) << 4);

    #pragma unroll
    for (int it = 0; it < 2; it++) {
        uint32_t c16 = (uint32_t)(lc + it * 4) * 16;
        uint32_t dof = (uint32_t)lr * 128 + (c16 ^ lxm);
        cp16(sbase + AT_K0 + dof, kh + (size_t)lr * 64 + (c16 >> 1));
        cp16(sbase + AT_V0 + dof, vh + (size_t)lr * TT + (c16 >> 1));
    }
    asm volatile("cp.async.commit_group;");

    const uint32_t* qw = (const uint32_t*)(q + (size_t)bh * TT * 64);
    uint32_t qf[4][4];
    #pragma unroll
    for (int kk = 0; kk < 4; kk++) {
        int kb = kk * 8;
        qf[kk][0] = qw[qg0 * 32 + kb + qq];
        qf[kk][1] = qw[qg1 * 32 + kb + qq];
        qf[kk][2] = qw[qg0 * 32 + kb + qq + 4];
        qf[kk][3] = qw[qg1 * 32 + kb + qq + 4];
    }

    float Oa[8][4];
    #pragma unroll
    for (int nt = 0; nt < 8; nt++)
        #pragma unroll
        for (int e = 0; e < 4; e++) Oa[nt][e] = 0.f;
    float m0 = -1e30f, m1 = -1e30f, l0 = 0.f, l1 = 0.f;

    for (int kt = 0; kt < ktiles; kt++) {
        asm volatile("cp.async.wait_group 0;");
        __syncthreads();
        if (kt + 1 < ktiles) {
            int nb = (kt + 1) & 1, k0n = (kt + 1) << 6;
            uint32_t kd = (nb ? AT_K1 : AT_K0), vd = (nb ? AT_V1 : AT_V0);
            #pragma unroll
            for (int it = 0; it < 2; it++) {
                uint32_t c16 = (uint32_t)(lc + it * 4) * 16;
                uint32_t dof = (uint32_t)lr * 128 + (c16 ^ lxm);
                cp16(sbase + kd + dof, kh + (size_t)(k0n + lr) * 64 + (c16 >> 1));
                cp16(sbase + vd + dof, vh + (size_t)lr * TT + k0n + (c16 >> 1));
            }
            asm volatile("cp.async.commit_group;");
        }
        uint32_t Ks = sbase + ((kt & 1) ? AT_K1 : AT_K0);
        uint32_t Vs = sbase + ((kt & 1) ? AT_V1 : AT_V0);
        int k0 = kt << 6;

        float s[8][4];
        #pragma unroll
        for (int nt = 0; nt < 8; nt++)
            #pragma unroll
            for (int e = 0; e < 4; e++) s[nt][e] = 0.f;
        #pragma unroll
        for (int kk = 0; kk < 4; kk++) {
            uint32_t bf[8][2];
            #pragma unroll
            for (int pr = 0; pr < 4; pr++)
                ldsm4(bf[2*pr][0], bf[2*pr][1], bf[2*pr+1][0], bf[2*pr+1][1],
                      Ks + (bRow + pr * 16) * 128 + ((32u * kk + bSel) ^ xm));
            #pragma unroll
            for (int nt = 0; nt < 8; nt++)
                asm volatile(
                    "mma.sync.aligned.m16n8k16.row.col.f32.f16.f16.f32 "
                    "{%0,%1,%2,%3}, {%4,%5,%6,%7}, {%8,%9}, {%0,%1,%2,%3};"
                    : "+f"(s[nt][0]), "+f"(s[nt][1]), "+f"(s[nt][2]), "+f"(s[nt][3])
                    : "r"(qf[kk][0]), "r"(qf[kk][1]), "r"(qf[kk][2]), "r"(qf[kk][3]),
                      "r"(bf[nt][0]), "r"(bf[nt][1]));
        }
        if (k0 + 63 > qg0) {
            #pragma unroll
            for (int nt = 0; nt < 8; nt++) {
                int kg = k0 + nt * 8 + 2 * qq;
                if (kg     > qg0) s[nt][0] = -1e30f;
                if (kg + 1 > qg0) s[nt][1] = -1e30f;
                if (kg     > qg1) s[nt][2] = -1e30f;
                if (kg + 1 > qg1) s[nt][3] = -1e30f;
            }
        }
        float r0 = -1e30f, r1 = -1e30f;
        #pragma unroll
        for (int nt = 0; nt < 8; nt++) {
            r0 = fmaxf(r0, fmaxf(s[nt][0], s[nt][1]));
            r1 = fmaxf(r1, fmaxf(s[nt][2], s[nt][3]));
        }
        r0 = fmaxf(r0, __shfl_xor_sync(0xffffffffu, r0, 1));
        r0 = fmaxf(r0, __shfl_xor_sync(0xffffffffu, r0, 2));
        r1 = fmaxf(r1, __shfl_xor_sync(0xffffffffu, r1, 1));
        r1 = fmaxf(r1, __shfl_xor_sync(0xffffffffu, r1, 2));
        float mn0 = fmaxf(m0, r0), mn1 = fmaxf(m1, r1);
        float sc0 = __expf(m0 - mn0), sc1 = __expf(m1 - mn1);
        float rs0 = 0.f, rs1 = 0.f;
        #pragma unroll
        for (int nt = 0; nt < 8; nt++) {
            s[nt][0] = __expf(s[nt][0] - mn0);
            s[nt][1] = __expf(s[nt][1] - mn0);
            s[nt][2] = __expf(s[nt][2] - mn1);
            s[nt][3] = __expf(s[nt][3] - mn1);
            rs0 += s[nt][0] + s[nt][1];
            rs1 += s[nt][2] + s[nt][3];
        }
        rs0 += __shfl_xor_sync(0xffffffffu, rs0, 1);
        rs0 += __shfl_xor_sync(0xffffffffu, rs0, 2);
        rs1 += __shfl_xor_sync(0xffffffffu, rs1, 1);
        rs1 += __shfl_xor_sync(0xffffffffu, rs1, 2);
        l0 = l0 * sc0 + rs0;  l1 = l1 * sc1 + rs1;
        m0 = mn0;  m1 = mn1;
        #pragma unroll
        for (int nt = 0; nt < 8; nt++) {
            Oa[nt][0] *= sc0; Oa[nt][1] *= sc0;
            Oa[nt][2] *= sc1; Oa[nt][3] *= sc1;
        }

        // PV: A-frags from s regs (ownership match), B via ldmatrix on V rows (= d)
        #pragma unroll
        for (int kk = 0; kk < 4; kk++) {
            uint32_t af[4];
            af[0] = h2u(__floats2half2_rn(s[2*kk][0],   s[2*kk][1]));
            af[1] = h2u(__floats2half2_rn(s[2*kk][2],   s[2*kk][3]));
            af[2] = h2u(__floats2half2_rn(s[2*kk+1][0], s[2*kk+1][1]));
            af[3] = h2u(__floats2half2_rn(s[2*kk+1][2], s[2*kk+1][3]));
            uint32_t bf[8][2];
            #pragma unroll
            for (int pr = 0; pr < 4; pr++)
                ldsm4(bf[2*pr][0], bf[2*pr][1], bf[2*pr+1][0], bf[2*pr+1][1],
                      Vs + (bRow + pr * 16) * 128 + ((32u * kk + bSel) ^ xm));
            #pragma unroll
            for (int nt = 0; nt < 8; nt++)
                asm volatile(
                    "mma.sync.aligned.m16n8k16.row.col.f32.f16.f16.f32 "
                    "{%0,%1,%2,%3}, {%4,%5,%6,%7}, {%8,%9}, {%0,%1,%2,%3};"
                    : "+f"(Oa[nt][0]), "+f"(Oa[nt][1]), "+f"(Oa[nt][2]), "+f"(Oa[nt][3])
                    : "r"(af[0]), "r"(af[1]), "r"(af[2]), "r"(af[3]),
                      "r"(bf[nt][0]), "r"(bf[nt][1]));
        }
    }

    int b_ = bh / HEADS, h_ = bh % HEADS;
    float inv0 = 1.f / l0, inv1 = 1.f / l1;
    char* ob = (char*)o;
    int row0 = b_ * TT + qg0, row1 = b_ * TT + qg1;
    size_t blk0 = (size_t)((row0 >> 7) * 6 + h_) * 16384;
    size_t blk1 = (size_t)((row1 >> 7) * 6 + h_) * 16384;
    uint32_t rb0 = (uint32_t)(row0 & 127) * 128, rb1 = (uint32_t)(row1 & 127) * 128;
    #pragma unroll
    for (int nt = 0; nt < 8; nt++) {
        uint32_t co = (uint32_t)(nt * 8 + 2 * qq) * 2;
        *(__half2*)(ob + blk0 + sw128(rb0 + co)) = __floats2half2_rn(Oa[nt][0] * inv0, Oa[nt][1] * inv0);
        *(__half2*)(ob + blk1 + sw128(rb1 + co)) = __floats2half2_rn(Oa[nt][2] * inv1, Oa[nt][3] * inv1);
    }
}

// ---------------- launch ----------------
extern "C" void kernel_launch(void* const* d_in, const int* in_sizes, int n_in,
                              void* d_out, int out_size) {
    const float* x   = (const float*)d_in[0];
    const float* Wq  = (const float*)d_in[1];
    const float* Wk  = (const float*)d_in[2];
    const float* Wv  = (const float*)d_in[3];
    const float* Wp  = (const float*)d_in[4];
    const float* bp  = (const float*)d_in[5];
    const float* g1  = (const float*)d_in[6];
    const float* b1  = (const float*)d_in[7];
    const float* g2  = (const float*)d_in[8];
    const float* b2  = (const float*)d_in[9];
    const float* W1  = (const float*)d_in[10];
    const float* bf1 = (const float*)d_in[11];
    const float* W2  = (const float*)d_in[12];
    const float* bf2 = (const float*)d_in[13];
    float* out = (float*)d_out;

    __half *h, *q, *k, *v, *o, *h2, *ff, *wqkv, *wp, *w1t, *w2t;
    cudaGetSymbolAddress((void**)&h,    g_h);
    cudaGetSymbolAddress((void**)&q,    g_q);
    cudaGetSymbolAddress((void**)&k,    g_k);
    cudaGetSymbolAddress((void**)&v,    g_v);
    cudaGetSymbolAddress((void**)&o,    g_o);
    cudaGetSymbolAddress((void**)&h2,   g_h2);
    cudaGetSymbolAddress((void**)&ff,   g_ff);
    cudaGetSymbolAddress((void**)&wqkv, g_wqkv);
    cudaGetSymbolAddress((void**)&wp,   g_wp);
    cudaGetSymbolAddress((void**)&w1t,  g_w1t);
    cudaGetSymbolAddress((void**)&w2t,  g_w2t);

    static bool attr_done = false;
    if (!attr_done) {
        cudaFuncSetAttribute(attn3_kernel, cudaFuncAttributeMaxDynamicSharedMemorySize, (int)ATTN_SMEM);
        cudaFuncSetAttribute(hgemm<0>, cudaFuncAttributeMaxDynamicSharedMemorySize, (int)HG_SMEM);
        cudaFuncSetAttribute(hgemm<1>, cudaFuncAttributeMaxDynamicSharedMemorySize, (int)HG_SMEM);
        cudaFuncSetAttribute(hgemm<2>, cudaFuncAttributeMaxDynamicSharedMemorySize, (int)HG_SMEM);
        attr_done = true;
    }

    trans_all<<<1728, dim3(32, 8)>>>(Wq, Wk, Wv, Wp, W1, W2, wqkv, wp, w1t, w2t);
    ln_kernel<<<ROWS / 8, 256>>>(x, g1, b1, h);
    hgemm<0><<<dim3(9, ROWS/128), 256, HG_SMEM>>>(h, wqkv, nullptr, nullptr, nullptr, q, k, v, 1152, 384);
    attn3_kernel<<<dim3(TT/128, BB*HEADS), 256, ATTN_SMEM>>>(q, k, v, o);
    hgemm<1><<<dim3(3, ROWS/128), 256, HG_SMEM>>>(o, wp, bp, x, out, nullptr, nullptr, nullptr, 384, 384);
    ln_kernel<<<ROWS / 8, 256>>>(out, g2, b2, h2);
    hgemm<2><<<dim3(12, ROWS/128), 256, HG_SMEM>>>(h2, w1t, bf1, nullptr, ff, nullptr, nullptr, nullptr, 1536, 384);
    hgemm<1><<<dim3(3, ROWS/128), 256, HG_SMEM>>>(ff, w2t, bf2, out, out, nullptr, nullptr, nullptr, 384, 1536);
}